// round 12
// baseline (speedup 1.0000x reference)
#include <cuda_runtime.h>
#include <cuda_fp16.h>
#include <math.h>
#include <stdint.h>

#define TOK   16384
#define Dm    512
#define Tt    4096
#define Bb    4
#define Hh    8
#define HDm   64
#define Lnum  6
#define MLPD  2048

#define WSZP  (Dm*Dm)
#define WSZM  (Dm*MLPD)
#define SZ_QKV (3*WSZP)
#define OFF_QKV 0
#define OFF_WO (6*SZ_QKV)
#define OFF_W1 (OFF_WO + 6*WSZP)
#define OFF_W2 (OFF_W1 + 6*WSZM)
#define WTOT   (OFF_W2 + 6*WSZM)

// ---------------- scratch (device globals) ----------------
__device__ __align__(128) float g_x[TOK * Dm];
__device__ __align__(128) float g_pe[Tt * Dm];
__device__ __align__(128) float2 g_stats[TOK * 8];
__device__ __align__(128) __half g_qkvh[TOK * 3 * Dm];
__device__ __align__(128) __half g_a[TOK * Dm];
__device__ __align__(128) __half g_m[(size_t)TOK * MLPD];
__device__ __align__(128) __half g_wh[WTOT];

// ---------------- helpers ----------------
__device__ __forceinline__ uint32_t smem_u32(const void* p) {
    uint32_t a;
    asm("{ .reg .u64 t; cvta.to.shared.u64 t, %1; cvt.u32.u64 %0, t; }" : "=r"(a) : "l"(p));
    return a;
}
#define SWZ(o) ((o) ^ (((o) >> 3) & 0x70))

#define CP16(dst, src) \
    asm volatile("cp.async.cg.shared.global [%0], [%1], 16;" :: "r"(dst), "l"(src) : "memory")
#define CP_COMMIT() asm volatile("cp.async.commit_group;" ::: "memory")
#define CP_WAIT(n)  asm volatile("cp.async.wait_group %0;" :: "n"(n) : "memory")

__device__ __forceinline__ void ldsm4(uint32_t* r, uint32_t a) {
    asm volatile("ldmatrix.sync.aligned.m8n8.x4.shared.b16 {%0,%1,%2,%3}, [%4];"
                 : "=r"(r[0]), "=r"(r[1]), "=r"(r[2]), "=r"(r[3]) : "r"(a));
}
__device__ __forceinline__ void mma16816(float* c, const uint32_t* a,
                                         uint32_t b0, uint32_t b1) {
    asm volatile("mma.sync.aligned.m16n8k16.row.col.f32.f16.f16.f32 "
                 "{%0,%1,%2,%3},{%4,%5,%6,%7},{%8,%9},{%0,%1,%2,%3};"
                 : "+f"(c[0]), "+f"(c[1]), "+f"(c[2]), "+f"(c[3])
                 : "r"(a[0]), "r"(a[1]), "r"(a[2]), "r"(a[3]), "r"(b0), "r"(b1));
}
__device__ __forceinline__ void mma16816_h(uint32_t* c, const uint32_t* a,
                                           uint32_t b0, uint32_t b1) {
    asm volatile("mma.sync.aligned.m16n8k16.row.col.f16.f16.f16.f16 "
                 "{%0,%1},{%2,%3,%4,%5},{%6,%7},{%0,%1};"
                 : "+r"(c[0]), "+r"(c[1])
                 : "r"(a[0]), "r"(a[1]), "r"(a[2]), "r"(a[3]), "r"(b0), "r"(b1));
}
__device__ __forceinline__ uint32_t packh2(float a, float b) {
    __half2 h = __halves2half2(__float2half_rn(a), __float2half_rn(b));
    return *(uint32_t*)&h;
}

// ============================================================
// PE table
// ============================================================
__global__ void pe_kernel(float* __restrict__ pe) {
    int id = blockIdx.x * blockDim.x + threadIdx.x;
    int pos = id >> 8, i = id & 255;
    const float c = (float)(-9.210340371976184 / 512.0);
    float div = expf((float)(2 * i) * c);
    float ang = (float)pos * div;
    float s, co;
    sincosf(ang, &s, &co);
    pe[pos * Dm + i] = s;
    pe[pos * Dm + i + 256] = co;
}

// ============================================================
// Embedding + PE add, with LN-stats partials (no LN kernel!)
// warp covers 128 cols of one token; half-warp = one 64-col slot
// ============================================================
__global__ void embed_kernel(const int* __restrict__ inputs,
                             const float* __restrict__ embed,
                             const float* __restrict__ pe,
                             float* __restrict__ x,
                             float2* __restrict__ stats) {
    size_t q = (size_t)blockIdx.x * blockDim.x + threadIdx.x;
    int token = (int)(q >> 7);
    int c4 = (int)(q & 127);
    int pos = token & (Tt - 1);
    int tok = inputs[token];
    float4 e = ((const float4*)(embed + (size_t)tok * Dm))[c4];
    float4 p = ((const float4*)(pe + (size_t)pos * Dm))[c4];
    float4 v = make_float4(e.x + p.x, e.y + p.y, e.z + p.z, e.w + p.w);
    ((float4*)(x + (size_t)token * Dm))[c4] = v;

    float s = v.x + v.y + v.z + v.w;
    float sq = v.x * v.x + v.y * v.y + v.z * v.z + v.w * v.w;
#pragma unroll
    for (int o = 8; o; o >>= 1) {
        s  += __shfl_xor_sync(0xffffffffu, s, o);
        sq += __shfl_xor_sync(0xffffffffu, sq, o);
    }
    if ((c4 & 15) == 0)
        stats[(size_t)token * 8 + (c4 >> 4)] = make_float2(s, sq);
}

// ============================================================
// Fused weight prep (one launch): fp32 [K][N] -> fp16 [N][K]
// ============================================================
__global__ void wprep_all(const float* __restrict__ wq, const float* __restrict__ wk,
                          const float* __restrict__ wv, const float* __restrict__ wo,
                          const float* __restrict__ w1, const float* __restrict__ w2,
                          __half* __restrict__ wh) {
    __shared__ float tt[32][33];
    int t = blockIdx.x;
    const float* src;
    __half* dh;
    int srcN, dstK, n0, k0, nd;

    if (t < 4608) {
        int g = t / 1536, r = t % 1536;
        int l = r >> 8, rr = r & 255;
        n0 = (rr & 15) << 5; k0 = (rr >> 4) << 5;
        const float* w = (g == 0) ? wq : (g == 1) ? wk : wv;
        src = w + (size_t)l * WSZP;
        dh = wh + OFF_QKV + (size_t)l * SZ_QKV;
        srcN = 512; dstK = 512; nd = g * 512 + n0;
    } else if (t < 6144) {
        int r = t - 4608;
        int l = r >> 8, rr = r & 255;
        n0 = (rr & 15) << 5; k0 = (rr >> 4) << 5;
        src = wo + (size_t)l * WSZP;
        dh = wh + OFF_WO + (size_t)l * WSZP;
        srcN = 512; dstK = 512; nd = n0;
    } else if (t < 12288) {
        int r = t - 6144;
        int l = r >> 10, rr = r & 1023;
        n0 = (rr & 63) << 5; k0 = (rr >> 6) << 5;
        src = w1 + (size_t)l * WSZM;
        dh = wh + OFF_W1 + (size_t)l * WSZM;
        srcN = 2048; dstK = 512; nd = n0;
    } else {
        int r = t - 12288;
        int l = r >> 10, rr = r & 1023;
        n0 = (rr & 15) << 5; k0 = (rr >> 4) << 5;
        src = w2 + (size_t)l * WSZM;
        dh = wh + OFF_W2 + (size_t)l * WSZM;
        srcN = 512; dstK = 2048; nd = n0;
    }

    int tx = threadIdx.x, ty = threadIdx.y;
#pragma unroll
    for (int i = 0; i < 4; i++)
        tt[ty + i * 8][tx] = src[(size_t)(k0 + ty + i * 8) * srcN + n0 + tx];
    __syncthreads();
#pragma unroll
    for (int i = 0; i < 4; i++) {
        float v = tt[tx][ty + i * 8];
        dh[(size_t)(nd + ty + i * 8) * dstK + k0 + tx] = __float2half_rn(v);
    }
}

// ============================================================
// Final LayerNorm (fp32 out) — unchanged proven path
// ============================================================
__global__ void ln_final(const float* __restrict__ x,
                         const float* __restrict__ sc,
                         const float* __restrict__ bi,
                         float* __restrict__ outf) {
    __shared__ float red[4];
    int t = blockIdx.x;
    int tid = threadIdx.x;
    float4 v = ((const float4*)(x + (size_t)t * Dm))[tid];

    float sum = v.x + v.y + v.z + v.w;
#pragma unroll
    for (int o = 16; o; o >>= 1) sum += __shfl_xor_sync(0xffffffffu, sum, o);
    if ((tid & 31) == 0) red[tid >> 5] = sum;
    __syncthreads();
    float mean = (red[0] + red[1] + red[2] + red[3]) * (1.f / Dm);
    __syncthreads();

    float dx = v.x - mean, dy = v.y - mean, dz = v.z - mean, dw = v.w - mean;
    float sq = dx * dx + dy * dy + dz * dz + dw * dw;
#pragma unroll
    for (int o = 16; o; o >>= 1) sq += __shfl_xor_sync(0xffffffffu, sq, o);
    if ((tid & 31) == 0) red[tid >> 5] = sq;
    __syncthreads();
    float var = (red[0] + red[1] + red[2] + red[3]) * (1.f / Dm);
    float rstd = rsqrtf(var + 1e-6f);

    float4 s4 = ((const float4*)sc)[tid];
    float4 b4 = ((const float4*)bi)[tid];
    ((float4*)(outf + (size_t)t * Dm))[tid] =
        make_float4(dx * rstd * s4.x + b4.x, dy * rstd * s4.y + b4.y,
                    dz * rstd * s4.z + b4.z, dw * rstd * s4.w + b4.w);
}

// ============================================================
// Unified HMMA fp16 GEMM.
// LNA:   A = LN(x) computed on the fly (fp32 x + stats + ln s/b)
// STATS: ACCUM epilogue also emits per-token (sum,sumsq) partials
// CTA 128x128, 8 warps, warp tile 32x64, K-chunk 64.
// Non-LNA: A+B 3-stage cp.async (32KB/stage).
// LNA:     A 2-stage STS (16KB) + B 3-stage cp.async (16KB) + muR.
// ============================================================
#define SMEM_STD 98304
#define SMEM_LNA (32768 + 49152 + 1024)

template <bool LNA, bool F16A, bool ACCUM, bool RELU, bool BIAS, bool WHF, bool STATS>
__global__ void __launch_bounds__(256, 2)
hgemm(const __half* __restrict__ A, const float* __restrict__ Ax,
      const float2* __restrict__ statsIn,
      const float* __restrict__ lnS, const float* __restrict__ lnB,
      const __half* __restrict__ B,
      const float* __restrict__ bias, float* __restrict__ C,
      __half* __restrict__ O, float2* __restrict__ statsOut,
      int N, int K) {
    extern __shared__ char smem[];
    uint32_t sb = smem_u32(smem);
    int tid = threadIdx.x, wid = tid >> 5, lane = tid & 31;
    int m0 = blockIdx.y * 128, n0 = blockIdx.x * 128;
    int wm = (wid >> 1) * 32, wn = (wid & 1) * 64;

    float accf[2][8][4];
    uint32_t acch[2][8][2];
    if (F16A) {
#pragma unroll
        for (int i = 0; i < 2; i++)
#pragma unroll
            for (int j = 0; j < 8; j++) { acch[i][j][0] = 0u; acch[i][j][1] = 0u; }
    } else {
#pragma unroll
        for (int i = 0; i < 2; i++)
#pragma unroll
            for (int j = 0; j < 8; j++)
#pragma unroll
                for (int e = 0; e < 4; e++) accf[i][j][e] = 0.f;
    }

    const int NC = K >> 6;

    // ---- LNA state ----
    int arow = tid >> 3, acolb = (tid & 7) * 8;
    float mu[4], rs_[4];
    float xr[4][8];
    float sreg[8], breg[8];
    float* muR = (float*)(smem + 81920);

#define LDGA(c) do { int kt_ = (c) << 6;                                        \
    _Pragma("unroll")                                                           \
    for (int i_ = 0; i_ < 4; i_++) {                                            \
        const float* xp_ = Ax + (size_t)(m0 + arow + i_ * 32) * K + kt_ + acolb;\
        float4 a0_ = *(const float4*)xp_;                                       \
        float4 a1_ = *(const float4*)(xp_ + 4);                                 \
        xr[i_][0]=a0_.x; xr[i_][1]=a0_.y; xr[i_][2]=a0_.z; xr[i_][3]=a0_.w;     \
        xr[i_][4]=a1_.x; xr[i_][5]=a1_.y; xr[i_][6]=a1_.z; xr[i_][7]=a1_.w; }   \
    float4 s0_ = *(const float4*)(lnS + kt_ + acolb);                           \
    float4 s1_ = *(const float4*)(lnS + kt_ + acolb + 4);                       \
    float4 b0_ = *(const float4*)(lnB + kt_ + acolb);                           \
    float4 b1_ = *(const float4*)(lnB + kt_ + acolb + 4);                       \
    sreg[0]=s0_.x; sreg[1]=s0_.y; sreg[2]=s0_.z; sreg[3]=s0_.w;                 \
    sreg[4]=s1_.x; sreg[5]=s1_.y; sreg[6]=s1_.z; sreg[7]=s1_.w;                 \
    breg[0]=b0_.x; breg[1]=b0_.y; breg[2]=b0_.z; breg[3]=b0_.w;                 \
    breg[4]=b1_.x; breg[5]=b1_.y; breg[6]=b1_.z; breg[7]=b1_.w; } while (0)

#define STS_A(c) do {                                                           \
    char* as_ = smem + ((c) & 1) * 16384;                                       \
    _Pragma("unroll")                                                           \
    for (int i_ = 0; i_ < 4; i_++) {                                            \
        uint32_t so_ = SWZ((uint32_t)((arow + i_ * 32) * 128 + (tid & 7) * 16));\
        uint32_t p0_ = packh2((xr[i_][0]-mu[i_])*rs_[i_]*sreg[0]+breg[0],       \
                              (xr[i_][1]-mu[i_])*rs_[i_]*sreg[1]+breg[1]);      \
        uint32_t p1_ = packh2((xr[i_][2]-mu[i_])*rs_[i_]*sreg[2]+breg[2],       \
                              (xr[i_][3]-mu[i_])*rs_[i_]*sreg[3]+breg[3]);      \
        uint32_t p2_ = packh2((xr[i_][4]-mu[i_])*rs_[i_]*sreg[4]+breg[4],       \
                              (xr[i_][5]-mu[i_])*rs_[i_]*sreg[5]+breg[5]);      \
        uint32_t p3_ = packh2((xr[i_][6]-mu[i_])*rs_[i_]*sreg[6]+breg[6],       \
                              (xr[i_][7]-mu[i_])*rs_[i_]*sreg[7]+breg[7]);      \
        *(uint4*)(as_ + so_) = make_uint4(p0_, p1_, p2_, p3_); } } while (0)

#define LOAD_B(c, s) do { int kt_ = (c) << 6;                                   \
    uint32_t bs_ = sb + 32768 + (s) * 16384;                                    \
    _Pragma("unroll")                                                           \
    for (int i_ = 0; i_ < 4; i_++) {                                            \
        int u_ = tid + i_ * 256; int row_ = u_ >> 3, kc_ = u_ & 7;              \
        uint32_t so_ = SWZ((uint32_t)(row_ * 128 + kc_ * 16));                  \
        CP16(bs_ + so_, B + (size_t)(n0 + row_) * K + kt_ + kc_ * 8); } } while (0)

#define LOAD_CHUNK(c, s) do { int kt_ = (c) << 6;                               \
    uint32_t st_ = sb + (s) * 32768;                                            \
    _Pragma("unroll")                                                           \
    for (int i_ = 0; i_ < 4; i_++) {                                            \
        int u_ = tid + i_ * 256; int row_ = u_ >> 3, kc_ = u_ & 7;              \
        uint32_t so_ = SWZ((uint32_t)(row_ * 128 + kc_ * 16));                  \
        CP16(st_ + so_,         A + (size_t)(m0 + row_) * K + kt_ + kc_ * 8);   \
        CP16(st_ + 16384 + so_, B + (size_t)(n0 + row_) * K + kt_ + kc_ * 8); } } while (0)

    if (LNA) {
        if (tid < 128) {
            float sx = 0.f, sq = 0.f;
#pragma unroll
            for (int p = 0; p < 8; p++) {
                float2 t2 = statsIn[(size_t)(m0 + tid) * 8 + p];
                sx += t2.x; sq += t2.y;
            }
            float mean = sx * (1.f / 512.f);
            float var = sq * (1.f / 512.f) - mean * mean;
            muR[tid * 2] = mean;
            muR[tid * 2 + 1] = rsqrtf(var + 1e-6f);
        }
        __syncthreads();
#pragma unroll
        for (int i = 0; i < 4; i++) {
            mu[i]  = muR[(arow + i * 32) * 2];
            rs_[i] = muR[(arow + i * 32) * 2 + 1];
        }
        LDGA(0);
        LOAD_B(0, 0); CP_COMMIT();
        LOAD_B(1, 1); CP_COMMIT();
    } else {
        LOAD_CHUNK(0, 0); CP_COMMIT();
        LOAD_CHUNK(1, 1); CP_COMMIT();
    }

    for (int c = 0; c < NC; c++) {
        if (LNA) STS_A(c);
        if (c + 1 < NC) { CP_WAIT(1); } else { CP_WAIT(0); }
        __syncthreads();
        if (LNA && c + 1 < NC) LDGA(c + 1);
        if (c + 2 < NC) {
            if (LNA) LOAD_B(c + 2, (c + 2) % 3);
            else     LOAD_CHUNK(c + 2, (c + 2) % 3);
            CP_COMMIT();
        }

        uint32_t stA, stB;
        if (LNA) { stA = sb + (c & 1) * 16384; stB = sb + 32768 + (c % 3) * 16384; }
        else     { stA = sb + (c % 3) * 32768; stB = stA + 16384; }

#pragma unroll
        for (int ks = 0; ks < 4; ks++) {
            int kb = ks * 32 + ((lane >> 4) & 1) * 16;
            uint32_t ah[2][4];
#pragma unroll
            for (int mf = 0; mf < 2; mf++) {
                uint32_t ro = (uint32_t)((wm + mf * 16 + (lane & 15)) * 128 + kb);
                ldsm4(ah[mf], stA + SWZ(ro));
            }
#pragma unroll
            for (int nf = 0; nf < 4; nf++) {
                uint32_t bh[4];
                uint32_t ro = (uint32_t)((wn + nf * 16 + (lane & 15)) * 128 + kb);
                ldsm4(bh, stB + SWZ(ro));
#pragma unroll
                for (int mf = 0; mf < 2; mf++)
#pragma unroll
                    for (int sl = 0; sl < 2; sl++) {
                        if (F16A)
                            mma16816_h(acch[mf][nf * 2 + sl], ah[mf], bh[sl], bh[sl + 2]);
                        else
                            mma16816(accf[mf][nf * 2 + sl], ah[mf], bh[sl], bh[sl + 2]);
                    }
            }
        }
    }

    // ---------------- epilogue ----------------
    int r0 = m0 + wm + (lane >> 2);
    int cb = n0 + wn + (lane & 3) * 2;
#pragma unroll
    for (int mf = 0; mf < 2; mf++)
#pragma unroll
        for (int hf = 0; hf < 2; hf++) {
            int rr = r0 + mf * 16 + hf * 8;
            float rsum = 0.f, rsq = 0.f;
#pragma unroll
            for (int nb = 0; nb < 8; nb++) {
                int cc = cb + nb * 8;
                if (F16A && WHF && !BIAS && !RELU && !ACCUM) {
                    *(uint32_t*)(O + (size_t)rr * N + cc) = acch[mf][nb][hf];
                    continue;
                }
                float v0, v1;
                if (F16A) {
                    __half2 hv = *(__half2*)&acch[mf][nb][hf];
                    v0 = __low2float(hv);
                    v1 = __high2float(hv);
                } else {
                    v0 = accf[mf][nb][hf * 2 + 0];
                    v1 = accf[mf][nb][hf * 2 + 1];
                }
                if (BIAS) {
                    float2 bv = *(const float2*)(bias + cc);
                    v0 += bv.x; v1 += bv.y;
                }
                if (RELU) { v0 = fmaxf(v0, 0.f); v1 = fmaxf(v1, 0.f); }
                if (ACCUM) {
                    float o0 = atomicAdd(C + (size_t)rr * N + cc, v0);
                    float o1 = atomicAdd(C + (size_t)rr * N + cc + 1, v1);
                    if (STATS) {
                        float nv0 = o0 + v0, nv1 = o1 + v1;
                        rsum += nv0 + nv1;
                        rsq  += nv0 * nv0 + nv1 * nv1;
                    }
                }
                if (WHF)
                    *(__half2*)(O + (size_t)rr * N + cc) =
                        __halves2half2(__float2half_rn(v0), __float2half_rn(v1));
            }
            if (STATS) {
                rsum += __shfl_xor_sync(0xffffffffu, rsum, 1);
                rsum += __shfl_xor_sync(0xffffffffu, rsum, 2);
                rsq  += __shfl_xor_sync(0xffffffffu, rsq, 1);
                rsq  += __shfl_xor_sync(0xffffffffu, rsq, 2);
                if ((lane & 3) == 0)
                    statsOut[(size_t)rr * 8 + ((n0 + wn) >> 6)] = make_float2(rsum, rsq);
            }
        }
#undef LDGA
#undef STS_A
#undef LOAD_B
#undef LOAD_CHUNK
}

// ============================================================
// Tensor-core local block attention (unchanged).
// ============================================================
#define AS_Q  0
#define AS_K  8192
#define AS_VT 16384
#define AS_MK 24576

__global__ void __launch_bounds__(128)
attn_mma(const __half* __restrict__ qkvh,
         const int* __restrict__ inputs,
         __half* __restrict__ aout,
         int lp) {
    __shared__ __align__(16) char smem[24576 + 256];
    uint32_t sb = smem_u32(smem);
    float* maskS = (float*)(smem + AS_MK);

    int n = blockIdx.x, h = blockIdx.y, b = blockIdx.z;
    int tid = threadIdx.x, wid = tid >> 5, lane = tid & 31;
    int base = n * 64 - lp;

#pragma unroll
    for (int i = 0; i < 4; i++) {
        int u = tid + i * 128;
        int row = u >> 3, c = u & 7;
        int gt = base + row;
        uint4 qv = make_uint4(0, 0, 0, 0), kv = qv, vv = qv;
        if (gt >= 0 && gt < Tt) {
            const __half* p = qkvh + ((size_t)(b * Tt + gt)) * 1536 + h * HDm;
            qv = *(const uint4*)(p + c * 8);
            kv = *(const uint4*)(p + 512 + c * 8);
            vv = *(const uint4*)(p + 1024 + c * 8);
        }
        uint32_t so = SWZ((uint32_t)(row * 128 + c * 16));
        *(uint4*)(smem + AS_Q + so) = qv;
        *(uint4*)(smem + AS_K + so) = kv;
        __half vh[8];
        *(uint4*)vh = vv;
#pragma unroll
        for (int j = 0; j < 8; j++) {
            uint32_t off = (uint32_t)((c * 8 + j) * 128 + row * 2);
            *(__half*)(smem + AS_VT + SWZ(off)) = vh[j];
        }
    }
    if (tid < 64) {
        int gt = base + tid;
        maskS[tid] = (gt >= 0 && gt < Tt && inputs[b * Tt + gt] > 0) ? 1.f : 0.f;
    }
    __syncthreads();

    int wm = wid * 16;

    float s[8][4];
#pragma unroll
    for (int j = 0; j < 8; j++)
#pragma unroll
        for (int e = 0; e < 4; e++) s[j][e] = 0.f;

#pragma unroll
    for (int ks = 0; ks < 4; ks++) {
        int kb = ks * 32 + ((lane >> 4) & 1) * 16;
        uint32_t a[4];
        ldsm4(a, sb + AS_Q + SWZ((uint32_t)((wm + (lane & 15)) * 128 + kb)));
#pragma unroll
        for (int nf = 0; nf < 4; nf++) {
            uint32_t bh[4];
            ldsm4(bh, sb + AS_K + SWZ((uint32_t)((nf * 16 + (lane & 15)) * 128 + kb)));
            mma16816(s[nf * 2 + 0], a, bh[0], bh[2]);
            mma16816(s[nf * 2 + 1], a, bh[1], bh[3]);
        }
    }

#pragma unroll
    for (int j = 0; j < 8; j++) {
        int col = j * 8 + (lane & 3) * 2;
        float m0 = maskS[col], m1 = maskS[col + 1];
        s[j][0] = (m0 > 0.f) ? s[j][0] * 0.125f : -1e9f;
        s[j][2] = (m0 > 0.f) ? s[j][2] * 0.125f : -1e9f;
        s[j][1] = (m1 > 0.f) ? s[j][1] * 0.125f : -1e9f;
        s[j][3] = (m1 > 0.f) ? s[j][3] * 0.125f : -1e9f;
    }

    float mx0 = -1e30f, mx1 = -1e30f;
#pragma unroll
    for (int j = 0; j < 8; j++) {
        mx0 = fmaxf(mx0, fmaxf(s[j][0], s[j][1]));
        mx1 = fmaxf(mx1, fmaxf(s[j][2], s[j][3]));
    }
    mx0 = fmaxf(mx0, __shfl_xor_sync(0xffffffffu, mx0, 1));
    mx0 = fmaxf(mx0, __shfl_xor_sync(0xffffffffu, mx0, 2));
    mx1 = fmaxf(mx1, __shfl_xor_sync(0xffffffffu, mx1, 1));
    mx1 = fmaxf(mx1, __shfl_xor_sync(0xffffffffu, mx1, 2));

    float sm0 = 0.f, sm1 = 0.f;
#pragma unroll
    for (int j = 0; j < 8; j++) {
        s[j][0] = expf(s[j][0] - mx0); sm0 += s[j][0];
        s[j][1] = expf(s[j][1] - mx0); sm0 += s[j][1];
        s[j][2] = expf(s[j][2] - mx1); sm1 += s[j][2];
        s[j][3] = expf(s[j][3] - mx1); sm1 += s[j][3];
    }
    sm0 += __shfl_xor_sync(0xffffffffu, sm0, 1);
    sm0 += __shfl_xor_sync(0xffffffffu, sm0, 2);
    sm1 += __shfl_xor_sync(0xffffffffu, sm1, 1);
    sm1 += __shfl_xor_sync(0xffffffffu, sm1, 2);
    float inv0 = 1.f / sm0, inv1 = 1.f / sm1;

    float o[8][4];
#pragma unroll
    for (int j = 0; j < 8; j++)
#pragma unroll
        for (int e = 0; e < 4; e++) o[j][e] = 0.f;

#pragma unroll
    for (int kk = 0; kk < 4; kk++) {
        uint32_t a[4];
        a[0] = packh2(s[2 * kk][0] * inv0, s[2 * kk][1] * inv0);
        a[1] = packh2(s[2 * kk][2] * inv1, s[2 * kk][3] * inv1);
        a[2] = packh2(s[2 * kk + 1][0] * inv0, s[2 * kk + 1][1] * inv0);
        a[3] = packh2(s[2 * kk + 1][2] * inv1, s[2 * kk + 1][3] * inv1);
        int kb = kk * 32 + ((lane >> 4) & 1) * 16;
#pragma unroll
        for (int nf = 0; nf < 4; nf++) {
            uint32_t bh[4];
            ldsm4(bh, sb + AS_VT + SWZ((uint32_t)((nf * 16 + (lane & 15)) * 128 + kb)));
            mma16816(o[nf * 2 + 0], a, bh[0], bh[2]);
            mma16816(o[nf * 2 + 1], a, bh[1], bh[3]);
        }
    }

    int r0 = base + wm + (lane >> 2);
    int r1 = r0 + 8;
#pragma unroll
    for (int j = 0; j < 8; j++) {
        int col = j * 8 + (lane & 3) * 2;
        if (r0 >= 0 && r0 < Tt)
            *(__half2*)(aout + ((size_t)(b * Tt + r0)) * Dm + h * HDm + col) =
                __halves2half2(__float2half_rn(o[j][0]), __float2half_rn(o[j][1]));
        if (r1 >= 0 && r1 < Tt)
            *(__half2*)(aout + ((size_t)(b * Tt + r1)) * Dm + h * HDm + col) =
                __halves2half2(__float2half_rn(o[j][2]), __float2half_rn(o[j][3]));
    }
}

// ============================================================
// Host driver
// ============================================================
extern "C" void kernel_launch(void* const* d_in, const int* in_sizes, int n_in,
                              void* d_out, int out_size) {
    const int*   inputs = (const int*)  d_in[0];
    const float* embed  = (const float*)d_in[1];
    const float* wq     = (const float*)d_in[2];
    const float* wk     = (const float*)d_in[3];
    const float* wv     = (const float*)d_in[4];
    const float* wo     = (const float*)d_in[5];
    const float* ln1_s  = (const float*)d_in[6];
    const float* ln1_b  = (const float*)d_in[7];
    const float* ln2_s  = (const float*)d_in[8];
    const float* ln2_b  = (const float*)d_in[9];
    const float* w1     = (const float*)d_in[10];
    const float* b1     = (const float*)d_in[11];
    const float* w2     = (const float*)d_in[12];
    const float* b2     = (const float*)d_in[13];
    const float* lnf_s  = (const float*)d_in[14];
    const float* lnf_b  = (const float*)d_in[15];

    float *x, *pe;
    float2* stats;
    __half *qkvh, *a, *m, *wh;
    cudaGetSymbolAddress((void**)&x,     g_x);
    cudaGetSymbolAddress((void**)&pe,    g_pe);
    cudaGetSymbolAddress((void**)&stats, g_stats);
    cudaGetSymbolAddress((void**)&qkvh,  g_qkvh);
    cudaGetSymbolAddress((void**)&a,     g_a);
    cudaGetSymbolAddress((void**)&m,     g_m);
    cudaGetSymbolAddress((void**)&wh,    g_wh);

    // instantiations:  LNA  F16A ACC  RELU BIAS WHF  STATS
    auto kQKV  = hgemm<true,  true, false,false,false,true, false>;
    auto kWO   = hgemm<false, true, true, false,false,false,true >;
    auto kMLP1 = hgemm<true,  true, false,true, true, true, false>;
    auto kMLP2 = hgemm<false, false,true, false,true, false,true >;
    cudaFuncSetAttribute(kQKV,  cudaFuncAttributeMaxDynamicSharedMemorySize, SMEM_LNA);
    cudaFuncSetAttribute(kWO,   cudaFuncAttributeMaxDynamicSharedMemorySize, SMEM_STD);
    cudaFuncSetAttribute(kMLP1, cudaFuncAttributeMaxDynamicSharedMemorySize, SMEM_LNA);
    cudaFuncSetAttribute(kMLP2, cudaFuncAttributeMaxDynamicSharedMemorySize, SMEM_STD);

    wprep_all<<<18432, dim3(32, 8)>>>(wq, wk, wv, wo, w1, w2, wh);
    pe_kernel<<<(Tt * 256) / 256, 256>>>(pe);
    embed_kernel<<<(TOK * Dm / 4) / 256, 256>>>(inputs, embed, pe, x, stats);

    dim3 gQKV(1536 / 128, TOK / 128);
    dim3 gP(Dm / 128, TOK / 128);
    dim3 gM1(MLPD / 128, TOK / 128);

    for (int l = 0; l < Lnum; l++) {
        int lp = (l & 1) ? 32 : 0;
        int nb = (l & 1) ? (Tt + 64) / 64 : Tt / 64;

        // qkv = LN1(x) @ [wq|wk|wv]  — LN fused, stats from prev producer
        kQKV<<<gQKV, 256, SMEM_LNA>>>(
            nullptr, x, stats, ln1_s + l * Dm, ln1_b + l * Dm,
            wh + OFF_QKV + (size_t)l * SZ_QKV,
            nullptr, nullptr, qkvh, nullptr, 1536, Dm);

        attn_mma<<<dim3(nb, Hh, Bb), 128>>>(qkvh, inputs, a, lp);

        // x += attn @ wo  — writes stats for LN2
        kWO<<<gP, 256, SMEM_STD>>>(
            a, nullptr, nullptr, nullptr, nullptr,
            wh + OFF_WO + (size_t)l * WSZP,
            nullptr, x, nullptr, stats, Dm, Dm);

        // m = relu(LN2(x) @ w1 + b1) — LN fused
        kMLP1<<<gM1, 256, SMEM_LNA>>>(
            nullptr, x, stats, ln2_s + l * Dm, ln2_b + l * Dm,
            wh + OFF_W1 + (size_t)l * WSZM,
            b1 + (size_t)l * MLPD, nullptr, m, nullptr, MLPD, Dm);

        // x += m @ w2 + b2 — writes stats for next LN1
        kMLP2<<<gP, 256, SMEM_STD>>>(
            m, nullptr, nullptr, nullptr, nullptr,
            wh + OFF_W2 + (size_t)l * WSZM,
            b2 + (size_t)l * Dm, x, nullptr, stats, Dm, MLPD);
    }

    ln_final<<<TOK, 128>>>(x, lnf_s, lnf_b, (float*)d_out);
}

// round 13
// speedup vs baseline: 1.3889x; 1.3889x over previous
#include <cuda_runtime.h>
#include <cuda_fp16.h>
#include <math.h>
#include <stdint.h>

#define TOK   16384
#define Dm    512
#define Tt    4096
#define Bb    4
#define Hh    8
#define HDm   64
#define Lnum  6
#define MLPD  2048

#define WSZP  (Dm*Dm)
#define WSZM  (Dm*MLPD)
#define SZ_QKV (3*WSZP)
#define OFF_QKV 0
#define OFF_WO (6*SZ_QKV)
#define OFF_W1 (OFF_WO + 6*WSZP)
#define OFF_W2 (OFF_W1 + 6*WSZM)
#define WTOT   (OFF_W2 + 6*WSZM)

// ---------------- scratch (device globals) ----------------
__device__ __align__(128) float g_x[TOK * Dm];
__device__ __align__(128) float g_pe[Tt * Dm];
__device__ __align__(128) float2 g_stats[TOK * 8];
__device__ __align__(128) __half g_qkvh[TOK * 3 * Dm];
__device__ __align__(128) __half g_h[TOK * Dm];
__device__ __align__(128) __half g_a[TOK * Dm];
__device__ __align__(128) __half g_m[(size_t)TOK * MLPD];
__device__ __align__(128) __half g_wh[WTOT];

// ---------------- helpers ----------------
__device__ __forceinline__ uint32_t smem_u32(const void* p) {
    uint32_t a;
    asm("{ .reg .u64 t; cvta.to.shared.u64 t, %1; cvt.u32.u64 %0, t; }" : "=r"(a) : "l"(p));
    return a;
}
#define SWZ(o) ((o) ^ (((o) >> 3) & 0x70))

#define CP16(dst, src) \
    asm volatile("cp.async.cg.shared.global [%0], [%1], 16;" :: "r"(dst), "l"(src) : "memory")
#define CP_COMMIT() asm volatile("cp.async.commit_group;" ::: "memory")
#define CP_WAIT(n)  asm volatile("cp.async.wait_group %0;" :: "n"(n) : "memory")

__device__ __forceinline__ void ldsm4(uint32_t* r, uint32_t a) {
    asm volatile("ldmatrix.sync.aligned.m8n8.x4.shared.b16 {%0,%1,%2,%3}, [%4];"
                 : "=r"(r[0]), "=r"(r[1]), "=r"(r[2]), "=r"(r[3]) : "r"(a));
}
__device__ __forceinline__ void mma16816(float* c, const uint32_t* a,
                                         uint32_t b0, uint32_t b1) {
    asm volatile("mma.sync.aligned.m16n8k16.row.col.f32.f16.f16.f32 "
                 "{%0,%1,%2,%3},{%4,%5,%6,%7},{%8,%9},{%0,%1,%2,%3};"
                 : "+f"(c[0]), "+f"(c[1]), "+f"(c[2]), "+f"(c[3])
                 : "r"(a[0]), "r"(a[1]), "r"(a[2]), "r"(a[3]), "r"(b0), "r"(b1));
}
__device__ __forceinline__ void mma16816_h(uint32_t* c, const uint32_t* a,
                                           uint32_t b0, uint32_t b1) {
    asm volatile("mma.sync.aligned.m16n8k16.row.col.f16.f16.f16.f16 "
                 "{%0,%1},{%2,%3,%4,%5},{%6,%7},{%0,%1};"
                 : "+r"(c[0]), "+r"(c[1])
                 : "r"(a[0]), "r"(a[1]), "r"(a[2]), "r"(a[3]), "r"(b0), "r"(b1));
}
__device__ __forceinline__ uint32_t packh2(float a, float b) {
    __half2 h = __halves2half2(__float2half_rn(a), __float2half_rn(b));
    return *(uint32_t*)&h;
}

// ============================================================
// PE table
// ============================================================
__global__ void pe_kernel(float* __restrict__ pe) {
    int id = blockIdx.x * blockDim.x + threadIdx.x;
    int pos = id >> 8, i = id & 255;
    const float c = (float)(-9.210340371976184 / 512.0);
    float div = expf((float)(2 * i) * c);
    float ang = (float)pos * div;
    float s, co;
    sincosf(ang, &s, &co);
    pe[pos * Dm + i] = s;
    pe[pos * Dm + i + 256] = co;
}

// ============================================================
// Embedding + PE add, emits LN-stats partials
// ============================================================
__global__ void embed_kernel(const int* __restrict__ inputs,
                             const float* __restrict__ embed,
                             const float* __restrict__ pe,
                             float* __restrict__ x,
                             float2* __restrict__ stats) {
    size_t q = (size_t)blockIdx.x * blockDim.x + threadIdx.x;
    int token = (int)(q >> 7);
    int c4 = (int)(q & 127);
    int pos = token & (Tt - 1);
    int tok = inputs[token];
    float4 e = ((const float4*)(embed + (size_t)tok * Dm))[c4];
    float4 p = ((const float4*)(pe + (size_t)pos * Dm))[c4];
    float4 v = make_float4(e.x + p.x, e.y + p.y, e.z + p.z, e.w + p.w);
    ((float4*)(x + (size_t)token * Dm))[c4] = v;

    float s = v.x + v.y + v.z + v.w;
    float sq = v.x * v.x + v.y * v.y + v.z * v.z + v.w * v.w;
#pragma unroll
    for (int o = 8; o; o >>= 1) {
        s  += __shfl_xor_sync(0xffffffffu, s, o);
        sq += __shfl_xor_sync(0xffffffffu, sq, o);
    }
    if ((c4 & 15) == 0)
        stats[(size_t)token * 8 + (c4 >> 4)] = make_float2(s, sq);
}

// ============================================================
// Fused weight prep (one launch): fp32 [K][N] -> fp16 [N][K]
// ============================================================
__global__ void wprep_all(const float* __restrict__ wq, const float* __restrict__ wk,
                          const float* __restrict__ wv, const float* __restrict__ wo,
                          const float* __restrict__ w1, const float* __restrict__ w2,
                          __half* __restrict__ wh) {
    __shared__ float tt[32][33];
    int t = blockIdx.x;
    const float* src;
    __half* dh;
    int srcN, dstK, n0, k0, nd;

    if (t < 4608) {
        int g = t / 1536, r = t % 1536;
        int l = r >> 8, rr = r & 255;
        n0 = (rr & 15) << 5; k0 = (rr >> 4) << 5;
        const float* w = (g == 0) ? wq : (g == 1) ? wk : wv;
        src = w + (size_t)l * WSZP;
        dh = wh + OFF_QKV + (size_t)l * SZ_QKV;
        srcN = 512; dstK = 512; nd = g * 512 + n0;
    } else if (t < 6144) {
        int r = t - 4608;
        int l = r >> 8, rr = r & 255;
        n0 = (rr & 15) << 5; k0 = (rr >> 4) << 5;
        src = wo + (size_t)l * WSZP;
        dh = wh + OFF_WO + (size_t)l * WSZP;
        srcN = 512; dstK = 512; nd = n0;
    } else if (t < 12288) {
        int r = t - 6144;
        int l = r >> 10, rr = r & 1023;
        n0 = (rr & 63) << 5; k0 = (rr >> 6) << 5;
        src = w1 + (size_t)l * WSZM;
        dh = wh + OFF_W1 + (size_t)l * WSZM;
        srcN = 2048; dstK = 512; nd = n0;
    } else {
        int r = t - 12288;
        int l = r >> 10, rr = r & 1023;
        n0 = (rr & 15) << 5; k0 = (rr >> 4) << 5;
        src = w2 + (size_t)l * WSZM;
        dh = wh + OFF_W2 + (size_t)l * WSZM;
        srcN = 512; dstK = 2048; nd = n0;
    }

    int tx = threadIdx.x, ty = threadIdx.y;
#pragma unroll
    for (int i = 0; i < 4; i++)
        tt[ty + i * 8][tx] = src[(size_t)(k0 + ty + i * 8) * srcN + n0 + tx];
    __syncthreads();
#pragma unroll
    for (int i = 0; i < 4; i++) {
        float v = tt[tx][ty + i * 8];
        dh[(size_t)(nd + ty + i * 8) * dstK + k0 + tx] = __float2half_rn(v);
    }
}

// ============================================================
// ln_apply: barrier-free LN using precomputed stats partials.
// One pass: read x (float4), apply, write fp16 (or fp32).
// Warp-aligned: 32 consecutive threads share one token.
// ============================================================
template <bool WHF>
__global__ void ln_apply(const float* __restrict__ x,
                         const float2* __restrict__ stats,
                         const float* __restrict__ sc,
                         const float* __restrict__ bi,
                         __half* __restrict__ oh,
                         float* __restrict__ outf) {
    int gid = blockIdx.x * blockDim.x + threadIdx.x;   // over TOK*128
    int t = gid >> 7, c4 = gid & 127;
    int lane = threadIdx.x & 31;

    float2 st = stats[(size_t)t * 8 + (lane & 7)];
    float s = st.x, sq = st.y;
#pragma unroll
    for (int o = 1; o < 8; o <<= 1) {
        s  += __shfl_xor_sync(0xffffffffu, s, o);
        sq += __shfl_xor_sync(0xffffffffu, sq, o);
    }
    float mean = s * (1.f / 512.f);
    float var = sq * (1.f / 512.f) - mean * mean;
    float rstd = rsqrtf(var + 1e-6f);

    float4 v = ((const float4*)(x + (size_t)t * Dm))[c4];
    float4 s4 = ((const float4*)sc)[c4];
    float4 b4 = ((const float4*)bi)[c4];
    float y0 = (v.x - mean) * rstd * s4.x + b4.x;
    float y1 = (v.y - mean) * rstd * s4.y + b4.y;
    float y2 = (v.z - mean) * rstd * s4.z + b4.z;
    float y3 = (v.w - mean) * rstd * s4.w + b4.w;

    if (WHF) {
        ((uint2*)(oh + (size_t)t * Dm))[c4] =
            make_uint2(packh2(y0, y1), packh2(y2, y3));
    } else {
        ((float4*)(outf + (size_t)t * Dm))[c4] = make_float4(y0, y1, y2, y3);
    }
}

// ============================================================
// HMMA fp16 GEMM (R11-proven mainloop): C[M,N] (+)= A @ B^T
// STATS: ACCUM epilogue also emits per-token (sum,sumsq) partials
// CTA 128x128, 8 warps, warp tile 32x64, K-chunk 64,
// 3-stage cp.async (32KB/stage), one sync per chunk.
// ============================================================
#define ST_B    16384
#define STAGE   32768
#define SMEM_GEMM (3 * STAGE)

template <bool F16A, bool ACCUM, bool RELU, bool BIAS, bool WF32, bool WHF, bool STATS>
__global__ void __launch_bounds__(256, 2)
hgemm(const __half* __restrict__ A, const __half* __restrict__ B,
      const float* __restrict__ bias, float* __restrict__ C,
      __half* __restrict__ O, float2* __restrict__ statsOut,
      int N, int K) {
    extern __shared__ char smem[];
    uint32_t sb = smem_u32(smem);
    int tid = threadIdx.x, wid = tid >> 5, lane = tid & 31;
    int m0 = blockIdx.y * 128, n0 = blockIdx.x * 128;
    int wm = (wid >> 1) * 32, wn = (wid & 1) * 64;

    float accf[2][8][4];
    uint32_t acch[2][8][2];
    if (F16A) {
#pragma unroll
        for (int i = 0; i < 2; i++)
#pragma unroll
            for (int j = 0; j < 8; j++) { acch[i][j][0] = 0u; acch[i][j][1] = 0u; }
    } else {
#pragma unroll
        for (int i = 0; i < 2; i++)
#pragma unroll
            for (int j = 0; j < 8; j++)
#pragma unroll
                for (int e = 0; e < 4; e++) accf[i][j][e] = 0.f;
    }

    const int NC = K >> 6;

#define LOAD_CHUNK(c, s) do {                                                   \
    int kt = (c) << 6;                                                          \
    uint32_t st_ = sb + (s) * STAGE;                                            \
    _Pragma("unroll")                                                           \
    for (int i = 0; i < 4; i++) {                                               \
        int u = tid + i * 256;                                                  \
        int row = u >> 3, kc = u & 7;                                           \
        uint32_t so = SWZ((uint32_t)(row * 128 + kc * 16));                     \
        size_t ga = (size_t)(m0 + row) * K + kt + kc * 8;                       \
        size_t gb = (size_t)(n0 + row) * K + kt + kc * 8;                       \
        CP16(st_ + so,        A + ga);                                          \
        CP16(st_ + ST_B + so, B + gb);                                          \
    } } while (0)

    LOAD_CHUNK(0, 0);
    CP_COMMIT();
    LOAD_CHUNK(1, 1);
    CP_COMMIT();

    for (int c = 0; c < NC; c++) {
        if (c + 1 < NC) { CP_WAIT(1); } else { CP_WAIT(0); }
        __syncthreads();
        if (c + 2 < NC) {
            LOAD_CHUNK(c + 2, (c + 2) % 3);
            CP_COMMIT();
        }
        uint32_t st = sb + (c % 3) * STAGE;

#pragma unroll
        for (int ks = 0; ks < 4; ks++) {
            int kb = ks * 32 + ((lane >> 4) & 1) * 16;
            uint32_t ah[2][4];
#pragma unroll
            for (int mf = 0; mf < 2; mf++) {
                uint32_t ro = (uint32_t)((wm + mf * 16 + (lane & 15)) * 128 + kb);
                ldsm4(ah[mf], st + SWZ(ro));
            }
#pragma unroll
            for (int nf = 0; nf < 4; nf++) {
                uint32_t bh[4];
                uint32_t ro = (uint32_t)((wn + nf * 16 + (lane & 15)) * 128 + kb);
                ldsm4(bh, st + ST_B + SWZ(ro));
#pragma unroll
                for (int mf = 0; mf < 2; mf++)
#pragma unroll
                    for (int sl = 0; sl < 2; sl++) {
                        if (F16A)
                            mma16816_h(acch[mf][nf * 2 + sl], ah[mf], bh[sl], bh[sl + 2]);
                        else
                            mma16816(accf[mf][nf * 2 + sl], ah[mf], bh[sl], bh[sl + 2]);
                    }
            }
        }
    }

    // epilogue
    int r0 = m0 + wm + (lane >> 2);
    int cb = n0 + wn + (lane & 3) * 2;
#pragma unroll
    for (int mf = 0; mf < 2; mf++)
#pragma unroll
        for (int hf = 0; hf < 2; hf++) {
            int rr = r0 + mf * 16 + hf * 8;
            float rsum = 0.f, rsq = 0.f;
#pragma unroll
            for (int nb = 0; nb < 8; nb++) {
                int cc = cb + nb * 8;
                if (F16A && WHF && !BIAS && !RELU && !ACCUM) {
                    *(uint32_t*)(O + (size_t)rr * N + cc) = acch[mf][nb][hf];
                    continue;
                }
                float v0, v1;
                if (F16A) {
                    __half2 hv = *(__half2*)&acch[mf][nb][hf];
                    v0 = __low2float(hv);
                    v1 = __high2float(hv);
                } else {
                    v0 = accf[mf][nb][hf * 2 + 0];
                    v1 = accf[mf][nb][hf * 2 + 1];
                }
                if (BIAS) {
                    float2 bv = *(const float2*)(bias + cc);
                    v0 += bv.x; v1 += bv.y;
                }
                if (RELU) { v0 = fmaxf(v0, 0.f); v1 = fmaxf(v1, 0.f); }
                if (ACCUM) {
                    float o0 = atomicAdd(C + (size_t)rr * N + cc, v0);
                    float o1 = atomicAdd(C + (size_t)rr * N + cc + 1, v1);
                    if (STATS) {
                        float nv0 = o0 + v0, nv1 = o1 + v1;
                        rsum += nv0 + nv1;
                        rsq  += nv0 * nv0 + nv1 * nv1;
                    }
                } else if (WF32) {
                    *(float2*)(C + (size_t)rr * N + cc) = make_float2(v0, v1);
                }
                if (WHF)
                    *(__half2*)(O + (size_t)rr * N + cc) =
                        __halves2half2(__float2half_rn(v0), __float2half_rn(v1));
            }
            if (STATS) {
                rsum += __shfl_xor_sync(0xffffffffu, rsum, 1);
                rsum += __shfl_xor_sync(0xffffffffu, rsum, 2);
                rsq  += __shfl_xor_sync(0xffffffffu, rsq, 1);
                rsq  += __shfl_xor_sync(0xffffffffu, rsq, 2);
                if ((lane & 3) == 0)
                    statsOut[(size_t)rr * 8 + ((n0 + wn) >> 6)] = make_float2(rsum, rsq);
            }
        }
#undef LOAD_CHUNK
}

// ============================================================
// Tensor-core local block attention (unchanged, proven).
// ============================================================
#define AS_Q  0
#define AS_K  8192
#define AS_VT 16384
#define AS_MK 24576

__global__ void __launch_bounds__(128)
attn_mma(const __half* __restrict__ qkvh,
         const int* __restrict__ inputs,
         __half* __restrict__ aout,
         int lp) {
    __shared__ __align__(16) char smem[24576 + 256];
    uint32_t sb = smem_u32(smem);
    float* maskS = (float*)(smem + AS_MK);

    int n = blockIdx.x, h = blockIdx.y, b = blockIdx.z;
    int tid = threadIdx.x, wid = tid >> 5, lane = tid & 31;
    int base = n * 64 - lp;

#pragma unroll
    for (int i = 0; i < 4; i++) {
        int u = tid + i * 128;
        int row = u >> 3, c = u & 7;
        int gt = base + row;
        uint4 qv = make_uint4(0, 0, 0, 0), kv = qv, vv = qv;
        if (gt >= 0 && gt < Tt) {
            const __half* p = qkvh + ((size_t)(b * Tt + gt)) * 1536 + h * HDm;
            qv = *(const uint4*)(p + c * 8);
            kv = *(const uint4*)(p + 512 + c * 8);
            vv = *(const uint4*)(p + 1024 + c * 8);
        }
        uint32_t so = SWZ((uint32_t)(row * 128 + c * 16));
        *(uint4*)(smem + AS_Q + so) = qv;
        *(uint4*)(smem + AS_K + so) = kv;
        __half vh[8];
        *(uint4*)vh = vv;
#pragma unroll
        for (int j = 0; j < 8; j++) {
            uint32_t off = (uint32_t)((c * 8 + j) * 128 + row * 2);
            *(__half*)(smem + AS_VT + SWZ(off)) = vh[j];
        }
    }
    if (tid < 64) {
        int gt = base + tid;
        maskS[tid] = (gt >= 0 && gt < Tt && inputs[b * Tt + gt] > 0) ? 1.f : 0.f;
    }
    __syncthreads();

    int wm = wid * 16;

    float s[8][4];
#pragma unroll
    for (int j = 0; j < 8; j++)
#pragma unroll
        for (int e = 0; e < 4; e++) s[j][e] = 0.f;

#pragma unroll
    for (int ks = 0; ks < 4; ks++) {
        int kb = ks * 32 + ((lane >> 4) & 1) * 16;
        uint32_t a[4];
        ldsm4(a, sb + AS_Q + SWZ((uint32_t)((wm + (lane & 15)) * 128 + kb)));
#pragma unroll
        for (int nf = 0; nf < 4; nf++) {
            uint32_t bh[4];
            ldsm4(bh, sb + AS_K + SWZ((uint32_t)((nf * 16 + (lane & 15)) * 128 + kb)));
            mma16816(s[nf * 2 + 0], a, bh[0], bh[2]);
            mma16816(s[nf * 2 + 1], a, bh[1], bh[3]);
        }
    }

#pragma unroll
    for (int j = 0; j < 8; j++) {
        int col = j * 8 + (lane & 3) * 2;
        float m0 = maskS[col], m1 = maskS[col + 1];
        s[j][0] = (m0 > 0.f) ? s[j][0] * 0.125f : -1e9f;
        s[j][2] = (m0 > 0.f) ? s[j][2] * 0.125f : -1e9f;
        s[j][1] = (m1 > 0.f) ? s[j][1] * 0.125f : -1e9f;
        s[j][3] = (m1 > 0.f) ? s[j][3] * 0.125f : -1e9f;
    }

    float mx0 = -1e30f, mx1 = -1e30f;
#pragma unroll
    for (int j = 0; j < 8; j++) {
        mx0 = fmaxf(mx0, fmaxf(s[j][0], s[j][1]));
        mx1 = fmaxf(mx1, fmaxf(s[j][2], s[j][3]));
    }
    mx0 = fmaxf(mx0, __shfl_xor_sync(0xffffffffu, mx0, 1));
    mx0 = fmaxf(mx0, __shfl_xor_sync(0xffffffffu, mx0, 2));
    mx1 = fmaxf(mx1, __shfl_xor_sync(0xffffffffu, mx1, 1));
    mx1 = fmaxf(mx1, __shfl_xor_sync(0xffffffffu, mx1, 2));

    float sm0 = 0.f, sm1 = 0.f;
#pragma unroll
    for (int j = 0; j < 8; j++) {
        s[j][0] = expf(s[j][0] - mx0); sm0 += s[j][0];
        s[j][1] = expf(s[j][1] - mx0); sm0 += s[j][1];
        s[j][2] = expf(s[j][2] - mx1); sm1 += s[j][2];
        s[j][3] = expf(s[j][3] - mx1); sm1 += s[j][3];
    }
    sm0 += __shfl_xor_sync(0xffffffffu, sm0, 1);
    sm0 += __shfl_xor_sync(0xffffffffu, sm0, 2);
    sm1 += __shfl_xor_sync(0xffffffffu, sm1, 1);
    sm1 += __shfl_xor_sync(0xffffffffu, sm1, 2);
    float inv0 = 1.f / sm0, inv1 = 1.f / sm1;

    float o[8][4];
#pragma unroll
    for (int j = 0; j < 8; j++)
#pragma unroll
        for (int e = 0; e < 4; e++) o[j][e] = 0.f;

#pragma unroll
    for (int kk = 0; kk < 4; kk++) {
        uint32_t a[4];
        a[0] = packh2(s[2 * kk][0] * inv0, s[2 * kk][1] * inv0);
        a[1] = packh2(s[2 * kk][2] * inv1, s[2 * kk][3] * inv1);
        a[2] = packh2(s[2 * kk + 1][0] * inv0, s[2 * kk + 1][1] * inv0);
        a[3] = packh2(s[2 * kk + 1][2] * inv1, s[2 * kk + 1][3] * inv1);
        int kb = kk * 32 + ((lane >> 4) & 1) * 16;
#pragma unroll
        for (int nf = 0; nf < 4; nf++) {
            uint32_t bh[4];
            ldsm4(bh, sb + AS_VT + SWZ((uint32_t)((nf * 16 + (lane & 15)) * 128 + kb)));
            mma16816(o[nf * 2 + 0], a, bh[0], bh[2]);
            mma16816(o[nf * 2 + 1], a, bh[1], bh[3]);
        }
    }

    int r0 = base + wm + (lane >> 2);
    int r1 = r0 + 8;
#pragma unroll
    for (int j = 0; j < 8; j++) {
        int col = j * 8 + (lane & 3) * 2;
        if (r0 >= 0 && r0 < Tt)
            *(__half2*)(aout + ((size_t)(b * Tt + r0)) * Dm + h * HDm + col) =
                __halves2half2(__float2half_rn(o[j][0]), __float2half_rn(o[j][1]));
        if (r1 >= 0 && r1 < Tt)
            *(__half2*)(aout + ((size_t)(b * Tt + r1)) * Dm + h * HDm + col) =
                __halves2half2(__float2half_rn(o[j][2]), __float2half_rn(o[j][3]));
    }
}

// ============================================================
// Host driver
// ============================================================
extern "C" void kernel_launch(void* const* d_in, const int* in_sizes, int n_in,
                              void* d_out, int out_size) {
    const int*   inputs = (const int*)  d_in[0];
    const float* embed  = (const float*)d_in[1];
    const float* wq     = (const float*)d_in[2];
    const float* wk     = (const float*)d_in[3];
    const float* wv     = (const float*)d_in[4];
    const float* wo     = (const float*)d_in[5];
    const float* ln1_s  = (const float*)d_in[6];
    const float* ln1_b  = (const float*)d_in[7];
    const float* ln2_s  = (const float*)d_in[8];
    const float* ln2_b  = (const float*)d_in[9];
    const float* w1     = (const float*)d_in[10];
    const float* b1     = (const float*)d_in[11];
    const float* w2     = (const float*)d_in[12];
    const float* b2     = (const float*)d_in[13];
    const float* lnf_s  = (const float*)d_in[14];
    const float* lnf_b  = (const float*)d_in[15];

    float *x, *pe;
    float2* stats;
    __half *qkvh, *h, *a, *m, *wh;
    cudaGetSymbolAddress((void**)&x,     g_x);
    cudaGetSymbolAddress((void**)&pe,    g_pe);
    cudaGetSymbolAddress((void**)&stats, g_stats);
    cudaGetSymbolAddress((void**)&qkvh,  g_qkvh);
    cudaGetSymbolAddress((void**)&h,     g_h);
    cudaGetSymbolAddress((void**)&a,     g_a);
    cudaGetSymbolAddress((void**)&m,     g_m);
    cudaGetSymbolAddress((void**)&wh,    g_wh);

    // instantiations:      F16A ACC  RELU BIAS WF32 WHF  STATS
    auto kQKV  = hgemm<true, false,false,false,false,true, false>;
    auto kWO   = hgemm<true, true, false,false,false,false,true >;
    auto kMLP1 = hgemm<true, false,true, true, false,true, false>;
    auto kMLP2 = hgemm<false,true, false,true, false,false,true >;
    cudaFuncSetAttribute(kQKV,  cudaFuncAttributeMaxDynamicSharedMemorySize, SMEM_GEMM);
    cudaFuncSetAttribute(kWO,   cudaFuncAttributeMaxDynamicSharedMemorySize, SMEM_GEMM);
    cudaFuncSetAttribute(kMLP1, cudaFuncAttributeMaxDynamicSharedMemorySize, SMEM_GEMM);
    cudaFuncSetAttribute(kMLP2, cudaFuncAttributeMaxDynamicSharedMemorySize, SMEM_GEMM);

    wprep_all<<<18432, dim3(32, 8)>>>(wq, wk, wv, wo, w1, w2, wh);
    pe_kernel<<<(Tt * 256) / 256, 256>>>(pe);
    embed_kernel<<<(TOK * Dm / 4) / 256, 256>>>(inputs, embed, pe, x, stats);

    dim3 gQKV(1536 / 128, TOK / 128);
    dim3 gP(Dm / 128, TOK / 128);
    dim3 gM1(MLPD / 128, TOK / 128);
    int gLN = (TOK * 128) / 256;

    for (int l = 0; l < Lnum; l++) {
        int lp = (l & 1) ? 32 : 0;
        int nb = (l & 1) ? (Tt + 64) / 64 : Tt / 64;

        // h = LN1(x) — barrier-free apply using stats
        ln_apply<true><<<gLN, 256>>>(x, stats, ln1_s + l * Dm, ln1_b + l * Dm,
                                     h, nullptr);

        // qkv (fp16) = h @ [wq|wk|wv]
        kQKV<<<gQKV, 256, SMEM_GEMM>>>(
            h, wh + OFF_QKV + (size_t)l * SZ_QKV,
            nullptr, nullptr, qkvh, nullptr, 1536, Dm);

        attn_mma<<<dim3(nb, Hh, Bb), 128>>>(qkvh, inputs, a, lp);

        // x += attn @ wo  — emits stats for LN2
        kWO<<<gP, 256, SMEM_GEMM>>>(
            a, wh + OFF_WO + (size_t)l * WSZP,
            nullptr, x, nullptr, stats, Dm, Dm);

        // h = LN2(x)
        ln_apply<true><<<gLN, 256>>>(x, stats, ln2_s + l * Dm, ln2_b + l * Dm,
                                     h, nullptr);

        // m = relu(h @ w1 + b1)
        kMLP1<<<gM1, 256, SMEM_GEMM>>>(
            h, wh + OFF_W1 + (size_t)l * WSZM,
            b1 + (size_t)l * MLPD, nullptr, m, nullptr, MLPD, Dm);

        // x += m @ w2 + b2 — emits stats for next LN1 / final LN
        kMLP2<<<gP, 256, SMEM_GEMM>>>(
            m, wh + OFF_W2 + (size_t)l * WSZM,
            b2 + (size_t)l * Dm, x, nullptr, stats, Dm, MLPD);
    }

    // final LN (fp32 out) — same barrier-free path
    ln_apply<false><<<gLN, 256>>>(x, stats, lnf_s, lnf_b,
                                  nullptr, (float*)d_out);
}

// round 14
// speedup vs baseline: 1.5032x; 1.0823x over previous
#include <cuda_runtime.h>
#include <cuda_fp16.h>
#include <math.h>
#include <stdint.h>

#define TOK   16384
#define Dm    512
#define Tt    4096
#define Bb    4
#define Hh    8
#define HDm   64
#define Lnum  6
#define MLPD  2048

#define WSZP  (Dm*Dm)
#define WSZM  (Dm*MLPD)
#define SZ_QKV (3*WSZP)
#define OFF_QKV 0
#define OFF_WO (6*SZ_QKV)
#define OFF_W1 (OFF_WO + 6*WSZP)
#define OFF_W2 (OFF_W1 + 6*WSZM)
#define WTOT   (OFF_W2 + 6*WSZM)

// ---------------- scratch (device globals) ----------------
__device__ __align__(128) float g_x[TOK * Dm];
__device__ __align__(128) float g_pe[Tt * Dm];
__device__ __align__(128) __half g_qkvh[TOK * 3 * Dm];
__device__ __align__(128) __half g_h[TOK * Dm];
__device__ __align__(128) __half g_a[TOK * Dm];
__device__ __align__(128) __half g_m[(size_t)TOK * MLPD];
__device__ __align__(128) __half g_wh[WTOT];

// ---------------- helpers ----------------
__device__ __forceinline__ uint32_t smem_u32(const void* p) {
    uint32_t a;
    asm("{ .reg .u64 t; cvta.to.shared.u64 t, %1; cvt.u32.u64 %0, t; }" : "=r"(a) : "l"(p));
    return a;
}
#define SWZ(o) ((o) ^ (((o) >> 3) & 0x70))

#define CP16(dst, src) \
    asm volatile("cp.async.cg.shared.global [%0], [%1], 16;" :: "r"(dst), "l"(src) : "memory")
#define CP_COMMIT() asm volatile("cp.async.commit_group;" ::: "memory")
#define CP_WAIT(n)  asm volatile("cp.async.wait_group %0;" :: "n"(n) : "memory")

__device__ __forceinline__ void ldsm4(uint32_t* r, uint32_t a) {
    asm volatile("ldmatrix.sync.aligned.m8n8.x4.shared.b16 {%0,%1,%2,%3}, [%4];"
                 : "=r"(r[0]), "=r"(r[1]), "=r"(r[2]), "=r"(r[3]) : "r"(a));
}
__device__ __forceinline__ void mma16816(float* c, const uint32_t* a,
                                         uint32_t b0, uint32_t b1) {
    asm volatile("mma.sync.aligned.m16n8k16.row.col.f32.f16.f16.f32 "
                 "{%0,%1,%2,%3},{%4,%5,%6,%7},{%8,%9},{%0,%1,%2,%3};"
                 : "+f"(c[0]), "+f"(c[1]), "+f"(c[2]), "+f"(c[3])
                 : "r"(a[0]), "r"(a[1]), "r"(a[2]), "r"(a[3]), "r"(b0), "r"(b1));
}
__device__ __forceinline__ void mma16816_h(uint32_t* c, const uint32_t* a,
                                           uint32_t b0, uint32_t b1) {
    asm volatile("mma.sync.aligned.m16n8k16.row.col.f16.f16.f16.f16 "
                 "{%0,%1},{%2,%3,%4,%5},{%6,%7},{%0,%1};"
                 : "+r"(c[0]), "+r"(c[1])
                 : "r"(a[0]), "r"(a[1]), "r"(a[2]), "r"(a[3]), "r"(b0), "r"(b1));
}
__device__ __forceinline__ uint32_t packh2(float a, float b) {
    __half2 h = __halves2half2(__float2half_rn(a), __float2half_rn(b));
    return *(uint32_t*)&h;
}

// ============================================================
// PE table
// ============================================================
__global__ void pe_kernel(float* __restrict__ pe) {
    int id = blockIdx.x * blockDim.x + threadIdx.x;
    int pos = id >> 8, i = id & 255;
    const float c = (float)(-9.210340371976184 / 512.0);
    float div = expf((float)(2 * i) * c);
    float ang = (float)pos * div;
    float s, co;
    sincosf(ang, &s, &co);
    pe[pos * Dm + i] = s;
    pe[pos * Dm + i + 256] = co;
}

// ============================================================
// Embedding + PE add (pure bandwidth, float4)
// ============================================================
__global__ void embed_kernel(const int* __restrict__ inputs,
                             const float* __restrict__ embed,
                             const float* __restrict__ pe,
                             float* __restrict__ x) {
    size_t q = (size_t)blockIdx.x * blockDim.x + threadIdx.x;
    int token = (int)(q >> 7);
    int c4 = (int)(q & 127);
    int pos = token & (Tt - 1);
    int tok = inputs[token];
    float4 e = ((const float4*)(embed + (size_t)tok * Dm))[c4];
    float4 p = ((const float4*)(pe + (size_t)pos * Dm))[c4];
    ((float4*)(x + (size_t)token * Dm))[c4] =
        make_float4(e.x + p.x, e.y + p.y, e.z + p.z, e.w + p.w);
}

// ============================================================
// Fused weight prep (one launch): fp32 [K][N] -> fp16 [N][K]
// ============================================================
__global__ void wprep_all(const float* __restrict__ wq, const float* __restrict__ wk,
                          const float* __restrict__ wv, const float* __restrict__ wo,
                          const float* __restrict__ w1, const float* __restrict__ w2,
                          __half* __restrict__ wh) {
    __shared__ float tt[32][33];
    int t = blockIdx.x;
    const float* src;
    __half* dh;
    int srcN, dstK, n0, k0, nd;

    if (t < 4608) {
        int g = t / 1536, r = t % 1536;
        int l = r >> 8, rr = r & 255;
        n0 = (rr & 15) << 5; k0 = (rr >> 4) << 5;
        const float* w = (g == 0) ? wq : (g == 1) ? wk : wv;
        src = w + (size_t)l * WSZP;
        dh = wh + OFF_QKV + (size_t)l * SZ_QKV;
        srcN = 512; dstK = 512; nd = g * 512 + n0;
    } else if (t < 6144) {
        int r = t - 4608;
        int l = r >> 8, rr = r & 255;
        n0 = (rr & 15) << 5; k0 = (rr >> 4) << 5;
        src = wo + (size_t)l * WSZP;
        dh = wh + OFF_WO + (size_t)l * WSZP;
        srcN = 512; dstK = 512; nd = n0;
    } else if (t < 12288) {
        int r = t - 6144;
        int l = r >> 10, rr = r & 1023;
        n0 = (rr & 63) << 5; k0 = (rr >> 6) << 5;
        src = w1 + (size_t)l * WSZM;
        dh = wh + OFF_W1 + (size_t)l * WSZM;
        srcN = 2048; dstK = 512; nd = n0;
    } else {
        int r = t - 12288;
        int l = r >> 10, rr = r & 1023;
        n0 = (rr & 15) << 5; k0 = (rr >> 4) << 5;
        src = w2 + (size_t)l * WSZM;
        dh = wh + OFF_W2 + (size_t)l * WSZM;
        srcN = 512; dstK = 2048; nd = n0;
    }

    int tx = threadIdx.x, ty = threadIdx.y;
#pragma unroll
    for (int i = 0; i < 4; i++)
        tt[ty + i * 8][tx] = src[(size_t)(k0 + ty + i * 8) * srcN + n0 + tx];
    __syncthreads();
#pragma unroll
    for (int i = 0; i < 4; i++) {
        float v = tt[tx][ty + i * 8];
        dh[(size_t)(nd + ty + i * 8) * dstK + k0 + tx] = __float2half_rn(v);
    }
}

// ============================================================
// Warp-per-token single-pass LayerNorm (no barriers, no smem).
// 32 lanes x 16 floats; loads float4 at [lane + 32*i] (coalesced).
// ============================================================
template <bool WHF>
__global__ void ln_warp(const float* __restrict__ x,
                        const float* __restrict__ sc,
                        const float* __restrict__ bi,
                        __half* __restrict__ oh,
                        float* __restrict__ outf) {
    int t = (blockIdx.x * blockDim.x + threadIdx.x) >> 5;  // token
    int lane = threadIdx.x & 31;
    const float4* xr = (const float4*)(x + (size_t)t * Dm);

    float4 v[4];
    float s = 0.f, sq = 0.f;
#pragma unroll
    for (int i = 0; i < 4; i++) {
        v[i] = xr[lane + 32 * i];
        s  += v[i].x + v[i].y + v[i].z + v[i].w;
        sq += v[i].x * v[i].x + v[i].y * v[i].y + v[i].z * v[i].z + v[i].w * v[i].w;
    }
#pragma unroll
    for (int o = 16; o; o >>= 1) {
        s  += __shfl_xor_sync(0xffffffffu, s, o);
        sq += __shfl_xor_sync(0xffffffffu, sq, o);
    }
    float mean = s * (1.f / 512.f);
    float var = sq * (1.f / 512.f) - mean * mean;
    float rstd = rsqrtf(var + 1e-6f);

#pragma unroll
    for (int i = 0; i < 4; i++) {
        int c4 = lane + 32 * i;
        float4 s4 = ((const float4*)sc)[c4];
        float4 b4 = ((const float4*)bi)[c4];
        float y0 = (v[i].x - mean) * rstd * s4.x + b4.x;
        float y1 = (v[i].y - mean) * rstd * s4.y + b4.y;
        float y2 = (v[i].z - mean) * rstd * s4.z + b4.z;
        float y3 = (v[i].w - mean) * rstd * s4.w + b4.w;
        if (WHF) {
            ((uint2*)(oh + (size_t)t * Dm))[c4] =
                make_uint2(packh2(y0, y1), packh2(y2, y3));
        } else {
            ((float4*)(outf + (size_t)t * Dm))[c4] = make_float4(y0, y1, y2, y3);
        }
    }
}

// ============================================================
// HMMA fp16 GEMM (R11-proven): C[M,N] (+)= A @ B^T
// CTA 128x128, 8 warps, warp tile 32x64, K-chunk 64,
// 3-stage cp.async (32KB/stage), one sync per chunk.
// ============================================================
#define ST_B    16384
#define STAGE   32768
#define SMEM_GEMM (3 * STAGE)

template <bool F16A, bool ACCUM, bool RELU, bool BIAS, bool WF32, bool WHF>
__global__ void __launch_bounds__(256, 2)
hgemm(const __half* __restrict__ A, const __half* __restrict__ B,
      const float* __restrict__ bias, float* __restrict__ C,
      __half* __restrict__ O,
      int N, int K) {
    extern __shared__ char smem[];
    uint32_t sb = smem_u32(smem);
    int tid = threadIdx.x, wid = tid >> 5, lane = tid & 31;
    int m0 = blockIdx.y * 128, n0 = blockIdx.x * 128;
    int wm = (wid >> 1) * 32, wn = (wid & 1) * 64;

    float accf[2][8][4];
    uint32_t acch[2][8][2];
    if (F16A) {
#pragma unroll
        for (int i = 0; i < 2; i++)
#pragma unroll
            for (int j = 0; j < 8; j++) { acch[i][j][0] = 0u; acch[i][j][1] = 0u; }
    } else {
#pragma unroll
        for (int i = 0; i < 2; i++)
#pragma unroll
            for (int j = 0; j < 8; j++)
#pragma unroll
                for (int e = 0; e < 4; e++) accf[i][j][e] = 0.f;
    }

    const int NC = K >> 6;

#define LOAD_CHUNK(c, s) do {                                                   \
    int kt = (c) << 6;                                                          \
    uint32_t st_ = sb + (s) * STAGE;                                            \
    _Pragma("unroll")                                                           \
    for (int i = 0; i < 4; i++) {                                               \
        int u = tid + i * 256;                                                  \
        int row = u >> 3, kc = u & 7;                                           \
        uint32_t so = SWZ((uint32_t)(row * 128 + kc * 16));                     \
        size_t ga = (size_t)(m0 + row) * K + kt + kc * 8;                       \
        size_t gb = (size_t)(n0 + row) * K + kt + kc * 8;                       \
        CP16(st_ + so,        A + ga);                                          \
        CP16(st_ + ST_B + so, B + gb);                                          \
    } } while (0)

    LOAD_CHUNK(0, 0);
    CP_COMMIT();
    LOAD_CHUNK(1, 1);
    CP_COMMIT();

    for (int c = 0; c < NC; c++) {
        if (c + 1 < NC) { CP_WAIT(1); } else { CP_WAIT(0); }
        __syncthreads();
        if (c + 2 < NC) {
            LOAD_CHUNK(c + 2, (c + 2) % 3);
            CP_COMMIT();
        }
        uint32_t st = sb + (c % 3) * STAGE;

#pragma unroll
        for (int ks = 0; ks < 4; ks++) {
            int kb = ks * 32 + ((lane >> 4) & 1) * 16;
            uint32_t ah[2][4];
#pragma unroll
            for (int mf = 0; mf < 2; mf++) {
                uint32_t ro = (uint32_t)((wm + mf * 16 + (lane & 15)) * 128 + kb);
                ldsm4(ah[mf], st + SWZ(ro));
            }
#pragma unroll
            for (int nf = 0; nf < 4; nf++) {
                uint32_t bh[4];
                uint32_t ro = (uint32_t)((wn + nf * 16 + (lane & 15)) * 128 + kb);
                ldsm4(bh, st + ST_B + SWZ(ro));
#pragma unroll
                for (int mf = 0; mf < 2; mf++)
#pragma unroll
                    for (int sl = 0; sl < 2; sl++) {
                        if (F16A)
                            mma16816_h(acch[mf][nf * 2 + sl], ah[mf], bh[sl], bh[sl + 2]);
                        else
                            mma16816(accf[mf][nf * 2 + sl], ah[mf], bh[sl], bh[sl + 2]);
                    }
            }
        }
    }

    // epilogue
    int r0 = m0 + wm + (lane >> 2);
    int cb = n0 + wn + (lane & 3) * 2;
#pragma unroll
    for (int mf = 0; mf < 2; mf++)
#pragma unroll
        for (int hf = 0; hf < 2; hf++) {
            int rr = r0 + mf * 16 + hf * 8;
#pragma unroll
            for (int nb = 0; nb < 8; nb++) {
                int cc = cb + nb * 8;
                if (F16A && WHF && !BIAS && !RELU && !ACCUM) {
                    *(uint32_t*)(O + (size_t)rr * N + cc) = acch[mf][nb][hf];
                    continue;
                }
                float v0, v1;
                if (F16A) {
                    __half2 hv = *(__half2*)&acch[mf][nb][hf];
                    v0 = __low2float(hv);
                    v1 = __high2float(hv);
                } else {
                    v0 = accf[mf][nb][hf * 2 + 0];
                    v1 = accf[mf][nb][hf * 2 + 1];
                }
                if (BIAS) {
                    float2 bv = *(const float2*)(bias + cc);
                    v0 += bv.x; v1 += bv.y;
                }
                if (RELU) { v0 = fmaxf(v0, 0.f); v1 = fmaxf(v1, 0.f); }
                if (ACCUM) {
                    atomicAdd(C + (size_t)rr * N + cc, v0);
                    atomicAdd(C + (size_t)rr * N + cc + 1, v1);
                } else if (WF32) {
                    *(float2*)(C + (size_t)rr * N + cc) = make_float2(v0, v1);
                }
                if (WHF)
                    *(__half2*)(O + (size_t)rr * N + cc) =
                        __halves2half2(__float2half_rn(v0), __float2half_rn(v1));
            }
        }
#undef LOAD_CHUNK
}

// ============================================================
// Tensor-core local block attention (proven).
// ============================================================
#define AS_Q  0
#define AS_K  8192
#define AS_VT 16384
#define AS_MK 24576

__global__ void __launch_bounds__(128)
attn_mma(const __half* __restrict__ qkvh,
         const int* __restrict__ inputs,
         __half* __restrict__ aout,
         int lp) {
    __shared__ __align__(16) char smem[24576 + 256];
    uint32_t sb = smem_u32(smem);
    float* maskS = (float*)(smem + AS_MK);

    int n = blockIdx.x, h = blockIdx.y, b = blockIdx.z;
    int tid = threadIdx.x, wid = tid >> 5, lane = tid & 31;
    int base = n * 64 - lp;

#pragma unroll
    for (int i = 0; i < 4; i++) {
        int u = tid + i * 128;
        int row = u >> 3, c = u & 7;
        int gt = base + row;
        uint4 qv = make_uint4(0, 0, 0, 0), kv = qv, vv = qv;
        if (gt >= 0 && gt < Tt) {
            const __half* p = qkvh + ((size_t)(b * Tt + gt)) * 1536 + h * HDm;
            qv = *(const uint4*)(p + c * 8);
            kv = *(const uint4*)(p + 512 + c * 8);
            vv = *(const uint4*)(p + 1024 + c * 8);
        }
        uint32_t so = SWZ((uint32_t)(row * 128 + c * 16));
        *(uint4*)(smem + AS_Q + so) = qv;
        *(uint4*)(smem + AS_K + so) = kv;
        __half vh[8];
        *(uint4*)vh = vv;
#pragma unroll
        for (int j = 0; j < 8; j++) {
            uint32_t off = (uint32_t)((c * 8 + j) * 128 + row * 2);
            *(__half*)(smem + AS_VT + SWZ(off)) = vh[j];
        }
    }
    if (tid < 64) {
        int gt = base + tid;
        maskS[tid] = (gt >= 0 && gt < Tt && inputs[b * Tt + gt] > 0) ? 1.f : 0.f;
    }
    __syncthreads();

    int wm = wid * 16;

    float s[8][4];
#pragma unroll
    for (int j = 0; j < 8; j++)
#pragma unroll
        for (int e = 0; e < 4; e++) s[j][e] = 0.f;

#pragma unroll
    for (int ks = 0; ks < 4; ks++) {
        int kb = ks * 32 + ((lane >> 4) & 1) * 16;
        uint32_t a[4];
        ldsm4(a, sb + AS_Q + SWZ((uint32_t)((wm + (lane & 15)) * 128 + kb)));
#pragma unroll
        for (int nf = 0; nf < 4; nf++) {
            uint32_t bh[4];
            ldsm4(bh, sb + AS_K + SWZ((uint32_t)((nf * 16 + (lane & 15)) * 128 + kb)));
            mma16816(s[nf * 2 + 0], a, bh[0], bh[2]);
            mma16816(s[nf * 2 + 1], a, bh[1], bh[3]);
        }
    }

#pragma unroll
    for (int j = 0; j < 8; j++) {
        int col = j * 8 + (lane & 3) * 2;
        float m0 = maskS[col], m1 = maskS[col + 1];
        s[j][0] = (m0 > 0.f) ? s[j][0] * 0.125f : -1e9f;
        s[j][2] = (m0 > 0.f) ? s[j][2] * 0.125f : -1e9f;
        s[j][1] = (m1 > 0.f) ? s[j][1] * 0.125f : -1e9f;
        s[j][3] = (m1 > 0.f) ? s[j][3] * 0.125f : -1e9f;
    }

    float mx0 = -1e30f, mx1 = -1e30f;
#pragma unroll
    for (int j = 0; j < 8; j++) {
        mx0 = fmaxf(mx0, fmaxf(s[j][0], s[j][1]));
        mx1 = fmaxf(mx1, fmaxf(s[j][2], s[j][3]));
    }
    mx0 = fmaxf(mx0, __shfl_xor_sync(0xffffffffu, mx0, 1));
    mx0 = fmaxf(mx0, __shfl_xor_sync(0xffffffffu, mx0, 2));
    mx1 = fmaxf(mx1, __shfl_xor_sync(0xffffffffu, mx1, 1));
    mx1 = fmaxf(mx1, __shfl_xor_sync(0xffffffffu, mx1, 2));

    float sm0 = 0.f, sm1 = 0.f;
#pragma unroll
    for (int j = 0; j < 8; j++) {
        s[j][0] = expf(s[j][0] - mx0); sm0 += s[j][0];
        s[j][1] = expf(s[j][1] - mx0); sm0 += s[j][1];
        s[j][2] = expf(s[j][2] - mx1); sm1 += s[j][2];
        s[j][3] = expf(s[j][3] - mx1); sm1 += s[j][3];
    }
    sm0 += __shfl_xor_sync(0xffffffffu, sm0, 1);
    sm0 += __shfl_xor_sync(0xffffffffu, sm0, 2);
    sm1 += __shfl_xor_sync(0xffffffffu, sm1, 1);
    sm1 += __shfl_xor_sync(0xffffffffu, sm1, 2);
    float inv0 = 1.f / sm0, inv1 = 1.f / sm1;

    float o[8][4];
#pragma unroll
    for (int j = 0; j < 8; j++)
#pragma unroll
        for (int e = 0; e < 4; e++) o[j][e] = 0.f;

#pragma unroll
    for (int kk = 0; kk < 4; kk++) {
        uint32_t a[4];
        a[0] = packh2(s[2 * kk][0] * inv0, s[2 * kk][1] * inv0);
        a[1] = packh2(s[2 * kk][2] * inv1, s[2 * kk][3] * inv1);
        a[2] = packh2(s[2 * kk + 1][0] * inv0, s[2 * kk + 1][1] * inv0);
        a[3] = packh2(s[2 * kk + 1][2] * inv1, s[2 * kk + 1][3] * inv1);
        int kb = kk * 32 + ((lane >> 4) & 1) * 16;
#pragma unroll
        for (int nf = 0; nf < 4; nf++) {
            uint32_t bh[4];
            ldsm4(bh, sb + AS_VT + SWZ((uint32_t)((nf * 16 + (lane & 15)) * 128 + kb)));
            mma16816(o[nf * 2 + 0], a, bh[0], bh[2]);
            mma16816(o[nf * 2 + 1], a, bh[1], bh[3]);
        }
    }

    int r0 = base + wm + (lane >> 2);
    int r1 = r0 + 8;
#pragma unroll
    for (int j = 0; j < 8; j++) {
        int col = j * 8 + (lane & 3) * 2;
        if (r0 >= 0 && r0 < Tt)
            *(__half2*)(aout + ((size_t)(b * Tt + r0)) * Dm + h * HDm + col) =
                __halves2half2(__float2half_rn(o[j][0]), __float2half_rn(o[j][1]));
        if (r1 >= 0 && r1 < Tt)
            *(__half2*)(aout + ((size_t)(b * Tt + r1)) * Dm + h * HDm + col) =
                __halves2half2(__float2half_rn(o[j][2]), __float2half_rn(o[j][3]));
    }
}

// ============================================================
// Host driver
// ============================================================
extern "C" void kernel_launch(void* const* d_in, const int* in_sizes, int n_in,
                              void* d_out, int out_size) {
    const int*   inputs = (const int*)  d_in[0];
    const float* embed  = (const float*)d_in[1];
    const float* wq     = (const float*)d_in[2];
    const float* wk     = (const float*)d_in[3];
    const float* wv     = (const float*)d_in[4];
    const float* wo     = (const float*)d_in[5];
    const float* ln1_s  = (const float*)d_in[6];
    const float* ln1_b  = (const float*)d_in[7];
    const float* ln2_s  = (const float*)d_in[8];
    const float* ln2_b  = (const float*)d_in[9];
    const float* w1     = (const float*)d_in[10];
    const float* b1     = (const float*)d_in[11];
    const float* w2     = (const float*)d_in[12];
    const float* b2     = (const float*)d_in[13];
    const float* lnf_s  = (const float*)d_in[14];
    const float* lnf_b  = (const float*)d_in[15];

    float *x, *pe;
    __half *qkvh, *h, *a, *m, *wh;
    cudaGetSymbolAddress((void**)&x,    g_x);
    cudaGetSymbolAddress((void**)&pe,   g_pe);
    cudaGetSymbolAddress((void**)&qkvh, g_qkvh);
    cudaGetSymbolAddress((void**)&h,    g_h);
    cudaGetSymbolAddress((void**)&a,    g_a);
    cudaGetSymbolAddress((void**)&m,    g_m);
    cudaGetSymbolAddress((void**)&wh,   g_wh);

    // instantiations:      F16A ACC  RELU BIAS WF32 WHF
    auto kQKV  = hgemm<true, false,false,false,false,true >;
    auto kWO   = hgemm<true, true, false,false,true, false>;
    auto kMLP1 = hgemm<true, false,true, true, false,true >;
    auto kMLP2 = hgemm<false,true, false,true, true, false>;
    cudaFuncSetAttribute(kQKV,  cudaFuncAttributeMaxDynamicSharedMemorySize, SMEM_GEMM);
    cudaFuncSetAttribute(kWO,   cudaFuncAttributeMaxDynamicSharedMemorySize, SMEM_GEMM);
    cudaFuncSetAttribute(kMLP1, cudaFuncAttributeMaxDynamicSharedMemorySize, SMEM_GEMM);
    cudaFuncSetAttribute(kMLP2, cudaFuncAttributeMaxDynamicSharedMemorySize, SMEM_GEMM);

    wprep_all<<<18432, dim3(32, 8)>>>(wq, wk, wv, wo, w1, w2, wh);
    pe_kernel<<<(Tt * 256) / 256, 256>>>(pe);
    embed_kernel<<<(TOK * Dm / 4) / 256, 256>>>(inputs, embed, pe, x);

    dim3 gQKV(1536 / 128, TOK / 128);
    dim3 gP(Dm / 128, TOK / 128);
    dim3 gM1(MLPD / 128, TOK / 128);
    int gLN = (TOK * 32) / 256;

    for (int l = 0; l < Lnum; l++) {
        int lp = (l & 1) ? 32 : 0;
        int nb = (l & 1) ? (Tt + 64) / 64 : Tt / 64;

        // h = LN1(x) — warp-per-token, no barriers
        ln_warp<true><<<gLN, 256>>>(x, ln1_s + l * Dm, ln1_b + l * Dm, h, nullptr);

        // qkv (fp16) = h @ [wq|wk|wv]  (fp16 accum, direct store)
        kQKV<<<gQKV, 256, SMEM_GEMM>>>(
            h, wh + OFF_QKV + (size_t)l * SZ_QKV,
            nullptr, nullptr, qkvh, 1536, Dm);

        attn_mma<<<dim3(nb, Hh, Bb), 128>>>(qkvh, inputs, a, lp);

        // x += attn @ wo  (fp16 accum, fire-and-forget atomic)
        kWO<<<gP, 256, SMEM_GEMM>>>(
            a, wh + OFF_WO + (size_t)l * WSZP,
            nullptr, x, nullptr, Dm, Dm);

        // h = LN2(x)
        ln_warp<true><<<gLN, 256>>>(x, ln2_s + l * Dm, ln2_b + l * Dm, h, nullptr);

        // m = relu(h @ w1 + b1)  (fp16 accum, fp16 out)
        kMLP1<<<gM1, 256, SMEM_GEMM>>>(
            h, wh + OFF_W1 + (size_t)l * WSZM,
            b1 + (size_t)l * MLPD, nullptr, m, MLPD, Dm);

        // x += m @ w2 + b2  (fp32 accum — K=2048, fire-and-forget atomic)
        kMLP2<<<gP, 256, SMEM_GEMM>>>(
            m, wh + OFF_W2 + (size_t)l * WSZM,
            b2 + (size_t)l * Dm, x, nullptr, Dm, MLPD);
    }

    // final LN (fp32 out)
    ln_warp<false><<<gLN, 256>>>(x, lnf_s, lnf_b, nullptr, (float*)d_out);
}

// round 15
// speedup vs baseline: 1.5059x; 1.0018x over previous
#include <cuda_runtime.h>
#include <cuda_fp16.h>
#include <math.h>
#include <stdint.h>

#define TOK   16384
#define Dm    512
#define Tt    4096
#define Bb    4
#define Hh    8
#define HDm   64
#define Lnum  6
#define MLPD  2048

#define WSZP  (Dm*Dm)
#define WSZM  (Dm*MLPD)
#define SZ_QKV (3*WSZP)
#define OFF_QKV 0
#define OFF_WO (6*SZ_QKV)
#define OFF_W1 (OFF_WO + 6*WSZP)
#define OFF_W2 (OFF_W1 + 6*WSZM)
#define WTOT   (OFF_W2 + 6*WSZM)

// ---------------- scratch (device globals) ----------------
__device__ __align__(128) float g_x[TOK * Dm];
__device__ __align__(128) float g_pe[Tt * Dm];
__device__ __align__(128) __half g_qkvh[TOK * 3 * Dm];
__device__ __align__(128) __half g_h[TOK * Dm];
__device__ __align__(128) __half g_a[TOK * Dm];
__device__ __align__(128) __half g_m[(size_t)TOK * MLPD];
__device__ __align__(128) __half g_wh[WTOT];

// ---------------- helpers ----------------
__device__ __forceinline__ uint32_t smem_u32(const void* p) {
    uint32_t a;
    asm("{ .reg .u64 t; cvta.to.shared.u64 t, %1; cvt.u32.u64 %0, t; }" : "=r"(a) : "l"(p));
    return a;
}
#define SWZ(o) ((o) ^ (((o) >> 3) & 0x70))

#define CP16(dst, src) \
    asm volatile("cp.async.cg.shared.global [%0], [%1], 16;" :: "r"(dst), "l"(src) : "memory")
#define CP_COMMIT() asm volatile("cp.async.commit_group;" ::: "memory")
#define CP_WAIT(n)  asm volatile("cp.async.wait_group %0;" :: "n"(n) : "memory")

__device__ __forceinline__ void ldsm4(uint32_t* r, uint32_t a) {
    asm volatile("ldmatrix.sync.aligned.m8n8.x4.shared.b16 {%0,%1,%2,%3}, [%4];"
                 : "=r"(r[0]), "=r"(r[1]), "=r"(r[2]), "=r"(r[3]) : "r"(a));
}
__device__ __forceinline__ void mma16816(float* c, const uint32_t* a,
                                         uint32_t b0, uint32_t b1) {
    asm volatile("mma.sync.aligned.m16n8k16.row.col.f32.f16.f16.f32 "
                 "{%0,%1,%2,%3},{%4,%5,%6,%7},{%8,%9},{%0,%1,%2,%3};"
                 : "+f"(c[0]), "+f"(c[1]), "+f"(c[2]), "+f"(c[3])
                 : "r"(a[0]), "r"(a[1]), "r"(a[2]), "r"(a[3]), "r"(b0), "r"(b1));
}
__device__ __forceinline__ void mma16816_h(uint32_t* c, const uint32_t* a,
                                           uint32_t b0, uint32_t b1) {
    asm volatile("mma.sync.aligned.m16n8k16.row.col.f16.f16.f16.f16 "
                 "{%0,%1},{%2,%3,%4,%5},{%6,%7},{%0,%1};"
                 : "+r"(c[0]), "+r"(c[1])
                 : "r"(a[0]), "r"(a[1]), "r"(a[2]), "r"(a[3]), "r"(b0), "r"(b1));
}
__device__ __forceinline__ uint32_t packh2(float a, float b) {
    __half2 h = __halves2half2(__float2half_rn(a), __float2half_rn(b));
    return *(uint32_t*)&h;
}

// ============================================================
// PE table
// ============================================================
__global__ void pe_kernel(float* __restrict__ pe) {
    int id = blockIdx.x * blockDim.x + threadIdx.x;
    int pos = id >> 8, i = id & 255;
    const float c = (float)(-9.210340371976184 / 512.0);
    float div = expf((float)(2 * i) * c);
    float ang = (float)pos * div;
    float s, co;
    sincosf(ang, &s, &co);
    pe[pos * Dm + i] = s;
    pe[pos * Dm + i + 256] = co;
}

// ============================================================
// Embedding + PE add (pure bandwidth, float4)
// ============================================================
__global__ void embed_kernel(const int* __restrict__ inputs,
                             const float* __restrict__ embed,
                             const float* __restrict__ pe,
                             float* __restrict__ x) {
    size_t q = (size_t)blockIdx.x * blockDim.x + threadIdx.x;
    int token = (int)(q >> 7);
    int c4 = (int)(q & 127);
    int pos = token & (Tt - 1);
    int tok = inputs[token];
    float4 e = ((const float4*)(embed + (size_t)tok * Dm))[c4];
    float4 p = ((const float4*)(pe + (size_t)pos * Dm))[c4];
    ((float4*)(x + (size_t)token * Dm))[c4] =
        make_float4(e.x + p.x, e.y + p.y, e.z + p.z, e.w + p.w);
}

// ============================================================
// Fused weight prep (one launch): fp32 [K][N] -> fp16 [N][K]
// ============================================================
__global__ void wprep_all(const float* __restrict__ wq, const float* __restrict__ wk,
                          const float* __restrict__ wv, const float* __restrict__ wo,
                          const float* __restrict__ w1, const float* __restrict__ w2,
                          __half* __restrict__ wh) {
    __shared__ float tt[32][33];
    int t = blockIdx.x;
    const float* src;
    __half* dh;
    int srcN, dstK, n0, k0, nd;

    if (t < 4608) {
        int g = t / 1536, r = t % 1536;
        int l = r >> 8, rr = r & 255;
        n0 = (rr & 15) << 5; k0 = (rr >> 4) << 5;
        const float* w = (g == 0) ? wq : (g == 1) ? wk : wv;
        src = w + (size_t)l * WSZP;
        dh = wh + OFF_QKV + (size_t)l * SZ_QKV;
        srcN = 512; dstK = 512; nd = g * 512 + n0;
    } else if (t < 6144) {
        int r = t - 4608;
        int l = r >> 8, rr = r & 255;
        n0 = (rr & 15) << 5; k0 = (rr >> 4) << 5;
        src = wo + (size_t)l * WSZP;
        dh = wh + OFF_WO + (size_t)l * WSZP;
        srcN = 512; dstK = 512; nd = n0;
    } else if (t < 12288) {
        int r = t - 6144;
        int l = r >> 10, rr = r & 1023;
        n0 = (rr & 63) << 5; k0 = (rr >> 6) << 5;
        src = w1 + (size_t)l * WSZM;
        dh = wh + OFF_W1 + (size_t)l * WSZM;
        srcN = 2048; dstK = 512; nd = n0;
    } else {
        int r = t - 12288;
        int l = r >> 10, rr = r & 1023;
        n0 = (rr & 15) << 5; k0 = (rr >> 4) << 5;
        src = w2 + (size_t)l * WSZM;
        dh = wh + OFF_W2 + (size_t)l * WSZM;
        srcN = 512; dstK = 2048; nd = n0;
    }

    int tx = threadIdx.x, ty = threadIdx.y;
#pragma unroll
    for (int i = 0; i < 4; i++)
        tt[ty + i * 8][tx] = src[(size_t)(k0 + ty + i * 8) * srcN + n0 + tx];
    __syncthreads();
#pragma unroll
    for (int i = 0; i < 4; i++) {
        float v = tt[tx][ty + i * 8];
        dh[(size_t)(nd + ty + i * 8) * dstK + k0 + tx] = __float2half_rn(v);
    }
}

// ============================================================
// Warp-per-2-tokens single-pass LayerNorm.
// Two independent load/reduce chains hide latency;
// scale/bias loaded once, applied to both tokens.
// ============================================================
template <bool WHF>
__global__ void ln_warp(const float* __restrict__ x,
                        const float* __restrict__ sc,
                        const float* __restrict__ bi,
                        __half* __restrict__ oh,
                        float* __restrict__ outf) {
    int w = (blockIdx.x * blockDim.x + threadIdx.x) >> 5;
    int lane = threadIdx.x & 31;
    int t0 = w * 2;
    const float4* xr0 = (const float4*)(x + (size_t)t0 * Dm);
    const float4* xr1 = (const float4*)(x + (size_t)(t0 + 1) * Dm);

    float4 v0[4], v1[4];
    float s0 = 0.f, q0 = 0.f, s1 = 0.f, q1 = 0.f;
#pragma unroll
    for (int i = 0; i < 4; i++) {
        v0[i] = xr0[lane + 32 * i];
        v1[i] = xr1[lane + 32 * i];
        s0 += v0[i].x + v0[i].y + v0[i].z + v0[i].w;
        q0 += v0[i].x * v0[i].x + v0[i].y * v0[i].y + v0[i].z * v0[i].z + v0[i].w * v0[i].w;
        s1 += v1[i].x + v1[i].y + v1[i].z + v1[i].w;
        q1 += v1[i].x * v1[i].x + v1[i].y * v1[i].y + v1[i].z * v1[i].z + v1[i].w * v1[i].w;
    }
#pragma unroll
    for (int o = 16; o; o >>= 1) {
        s0 += __shfl_xor_sync(0xffffffffu, s0, o);
        q0 += __shfl_xor_sync(0xffffffffu, q0, o);
        s1 += __shfl_xor_sync(0xffffffffu, s1, o);
        q1 += __shfl_xor_sync(0xffffffffu, q1, o);
    }
    float mean0 = s0 * (1.f / 512.f);
    float rstd0 = rsqrtf(q0 * (1.f / 512.f) - mean0 * mean0 + 1e-6f);
    float mean1 = s1 * (1.f / 512.f);
    float rstd1 = rsqrtf(q1 * (1.f / 512.f) - mean1 * mean1 + 1e-6f);

#pragma unroll
    for (int i = 0; i < 4; i++) {
        int c4 = lane + 32 * i;
        float4 s4 = ((const float4*)sc)[c4];
        float4 b4 = ((const float4*)bi)[c4];
        float a0 = (v0[i].x - mean0) * rstd0 * s4.x + b4.x;
        float a1 = (v0[i].y - mean0) * rstd0 * s4.y + b4.y;
        float a2 = (v0[i].z - mean0) * rstd0 * s4.z + b4.z;
        float a3 = (v0[i].w - mean0) * rstd0 * s4.w + b4.w;
        float c0 = (v1[i].x - mean1) * rstd1 * s4.x + b4.x;
        float c1 = (v1[i].y - mean1) * rstd1 * s4.y + b4.y;
        float c2 = (v1[i].z - mean1) * rstd1 * s4.z + b4.z;
        float c3 = (v1[i].w - mean1) * rstd1 * s4.w + b4.w;
        if (WHF) {
            ((uint2*)(oh + (size_t)t0 * Dm))[c4] = make_uint2(packh2(a0, a1), packh2(a2, a3));
            ((uint2*)(oh + (size_t)(t0 + 1) * Dm))[c4] = make_uint2(packh2(c0, c1), packh2(c2, c3));
        } else {
            ((float4*)(outf + (size_t)t0 * Dm))[c4] = make_float4(a0, a1, a2, a3);
            ((float4*)(outf + (size_t)(t0 + 1) * Dm))[c4] = make_float4(c0, c1, c2, c3);
        }
    }
}

// ============================================================
// HMMA fp16 GEMM (R11-proven): C[M,N] (+)= A @ B^T
// CTA 128x128, 8 warps, warp tile 32x64, K-chunk 64,
// 3-stage cp.async (32KB/stage), one sync per chunk.
// ============================================================
#define ST_B    16384
#define STAGE   32768
#define SMEM_GEMM (3 * STAGE)

template <bool F16A, bool ACCUM, bool RELU, bool BIAS, bool WF32, bool WHF>
__global__ void __launch_bounds__(256, 2)
hgemm(const __half* __restrict__ A, const __half* __restrict__ B,
      const float* __restrict__ bias, float* __restrict__ C,
      __half* __restrict__ O,
      int N, int K) {
    extern __shared__ char smem[];
    uint32_t sb = smem_u32(smem);
    int tid = threadIdx.x, wid = tid >> 5, lane = tid & 31;
    int m0 = blockIdx.y * 128, n0 = blockIdx.x * 128;
    int wm = (wid >> 1) * 32, wn = (wid & 1) * 64;

    float accf[2][8][4];
    uint32_t acch[2][8][2];
    if (F16A) {
#pragma unroll
        for (int i = 0; i < 2; i++)
#pragma unroll
            for (int j = 0; j < 8; j++) { acch[i][j][0] = 0u; acch[i][j][1] = 0u; }
    } else {
#pragma unroll
        for (int i = 0; i < 2; i++)
#pragma unroll
            for (int j = 0; j < 8; j++)
#pragma unroll
                for (int e = 0; e < 4; e++) accf[i][j][e] = 0.f;
    }

    const int NC = K >> 6;

#define LOAD_CHUNK(c, s) do {                                                   \
    int kt = (c) << 6;                                                          \
    uint32_t st_ = sb + (s) * STAGE;                                            \
    _Pragma("unroll")                                                           \
    for (int i = 0; i < 4; i++) {                                               \
        int u = tid + i * 256;                                                  \
        int row = u >> 3, kc = u & 7;                                           \
        uint32_t so = SWZ((uint32_t)(row * 128 + kc * 16));                     \
        size_t ga = (size_t)(m0 + row) * K + kt + kc * 8;                       \
        size_t gb = (size_t)(n0 + row) * K + kt + kc * 8;                       \
        CP16(st_ + so,        A + ga);                                          \
        CP16(st_ + ST_B + so, B + gb);                                          \
    } } while (0)

    LOAD_CHUNK(0, 0);
    CP_COMMIT();
    LOAD_CHUNK(1, 1);
    CP_COMMIT();

    for (int c = 0; c < NC; c++) {
        if (c + 1 < NC) { CP_WAIT(1); } else { CP_WAIT(0); }
        __syncthreads();
        if (c + 2 < NC) {
            LOAD_CHUNK(c + 2, (c + 2) % 3);
            CP_COMMIT();
        }
        uint32_t st = sb + (c % 3) * STAGE;

#pragma unroll
        for (int ks = 0; ks < 4; ks++) {
            int kb = ks * 32 + ((lane >> 4) & 1) * 16;
            uint32_t ah[2][4];
#pragma unroll
            for (int mf = 0; mf < 2; mf++) {
                uint32_t ro = (uint32_t)((wm + mf * 16 + (lane & 15)) * 128 + kb);
                ldsm4(ah[mf], st + SWZ(ro));
            }
#pragma unroll
            for (int nf = 0; nf < 4; nf++) {
                uint32_t bh[4];
                uint32_t ro = (uint32_t)((wn + nf * 16 + (lane & 15)) * 128 + kb);
                ldsm4(bh, st + ST_B + SWZ(ro));
#pragma unroll
                for (int mf = 0; mf < 2; mf++)
#pragma unroll
                    for (int sl = 0; sl < 2; sl++) {
                        if (F16A)
                            mma16816_h(acch[mf][nf * 2 + sl], ah[mf], bh[sl], bh[sl + 2]);
                        else
                            mma16816(accf[mf][nf * 2 + sl], ah[mf], bh[sl], bh[sl + 2]);
                    }
            }
        }
    }

    // epilogue
    int r0 = m0 + wm + (lane >> 2);
    int cb = n0 + wn + (lane & 3) * 2;
#pragma unroll
    for (int mf = 0; mf < 2; mf++)
#pragma unroll
        for (int hf = 0; hf < 2; hf++) {
            int rr = r0 + mf * 16 + hf * 8;
#pragma unroll
            for (int nb = 0; nb < 8; nb++) {
                int cc = cb + nb * 8;
                if (F16A && WHF && !BIAS && !RELU && !ACCUM) {
                    *(uint32_t*)(O + (size_t)rr * N + cc) = acch[mf][nb][hf];
                    continue;
                }
                float v0, v1;
                if (F16A) {
                    __half2 hv = *(__half2*)&acch[mf][nb][hf];
                    v0 = __low2float(hv);
                    v1 = __high2float(hv);
                } else {
                    v0 = accf[mf][nb][hf * 2 + 0];
                    v1 = accf[mf][nb][hf * 2 + 1];
                }
                if (BIAS) {
                    float2 bv = *(const float2*)(bias + cc);
                    v0 += bv.x; v1 += bv.y;
                }
                if (RELU) { v0 = fmaxf(v0, 0.f); v1 = fmaxf(v1, 0.f); }
                if (ACCUM) {
                    atomicAdd(C + (size_t)rr * N + cc, v0);
                    atomicAdd(C + (size_t)rr * N + cc + 1, v1);
                } else if (WF32) {
                    *(float2*)(C + (size_t)rr * N + cc) = make_float2(v0, v1);
                }
                if (WHF)
                    *(__half2*)(O + (size_t)rr * N + cc) =
                        __halves2half2(__float2half_rn(v0), __float2half_rn(v1));
            }
        }
#undef LOAD_CHUNK
}

// ============================================================
// Tensor-core local block attention — 2 heads per CTA.
// 256 threads, 8 warps: warps 0-3 -> head h0, warps 4-7 -> h0+1.
// Dynamic smem: Q/K/VT per head (3x8KB x2) + mask.
// ============================================================
#define AT_HEAD 24576
#define AT_MK   49152
#define SMEM_ATTN (49152 + 256)

__global__ void __launch_bounds__(256)
attn_mma(const __half* __restrict__ qkvh,
         const int* __restrict__ inputs,
         __half* __restrict__ aout,
         int lp) {
    extern __shared__ __align__(16) char smem[];
    uint32_t sb = smem_u32(smem);
    float* maskS = (float*)(smem + AT_MK);

    int n = blockIdx.x, h0 = blockIdx.y * 2, b = blockIdx.z;
    int tid = threadIdx.x, wid = tid >> 5, lane = tid & 31;
    int base = n * 64 - lp;

    // ---- load Q,K (swizzled) + V transposed, both heads ----
#pragma unroll
    for (int hh = 0; hh < 2; hh++) {
        char* hs = smem + hh * AT_HEAD;
#pragma unroll
        for (int i = 0; i < 2; i++) {
            int u = tid + i * 256;          // 512 units: row=u/8, chunk c=u%8
            int row = u >> 3, c = u & 7;
            int gt = base + row;
            uint4 qv = make_uint4(0, 0, 0, 0), kv = qv, vv = qv;
            if (gt >= 0 && gt < Tt) {
                const __half* p = qkvh + ((size_t)(b * Tt + gt)) * 1536 + (h0 + hh) * HDm;
                qv = *(const uint4*)(p + c * 8);
                kv = *(const uint4*)(p + 512 + c * 8);
                vv = *(const uint4*)(p + 1024 + c * 8);
            }
            uint32_t so = SWZ((uint32_t)(row * 128 + c * 16));
            *(uint4*)(hs + so) = qv;
            *(uint4*)(hs + 8192 + so) = kv;
            __half vh[8];
            *(uint4*)vh = vv;
#pragma unroll
            for (int j = 0; j < 8; j++) {
                uint32_t off = (uint32_t)((c * 8 + j) * 128 + row * 2);
                *(__half*)(hs + 16384 + SWZ(off)) = vh[j];
            }
        }
    }
    if (tid < 64) {
        int gt = base + tid;
        maskS[tid] = (gt >= 0 && gt < Tt && inputs[b * Tt + gt] > 0) ? 1.f : 0.f;
    }
    __syncthreads();

    int hh = wid >> 2;
    int wm = (wid & 3) * 16;
    uint32_t hb = sb + hh * AT_HEAD;
    int h = h0 + hh;

    // ---- S = Q @ K^T ----
    float s[8][4];
#pragma unroll
    for (int j = 0; j < 8; j++)
#pragma unroll
        for (int e = 0; e < 4; e++) s[j][e] = 0.f;

#pragma unroll
    for (int ks = 0; ks < 4; ks++) {
        int kb = ks * 32 + ((lane >> 4) & 1) * 16;
        uint32_t a[4];
        ldsm4(a, hb + SWZ((uint32_t)((wm + (lane & 15)) * 128 + kb)));
#pragma unroll
        for (int nf = 0; nf < 4; nf++) {
            uint32_t bh[4];
            ldsm4(bh, hb + 8192 + SWZ((uint32_t)((nf * 16 + (lane & 15)) * 128 + kb)));
            mma16816(s[nf * 2 + 0], a, bh[0], bh[2]);
            mma16816(s[nf * 2 + 1], a, bh[1], bh[3]);
        }
    }

#pragma unroll
    for (int j = 0; j < 8; j++) {
        int col = j * 8 + (lane & 3) * 2;
        float m0 = maskS[col], m1 = maskS[col + 1];
        s[j][0] = (m0 > 0.f) ? s[j][0] * 0.125f : -1e9f;
        s[j][2] = (m0 > 0.f) ? s[j][2] * 0.125f : -1e9f;
        s[j][1] = (m1 > 0.f) ? s[j][1] * 0.125f : -1e9f;
        s[j][3] = (m1 > 0.f) ? s[j][3] * 0.125f : -1e9f;
    }

    float mx0 = -1e30f, mx1 = -1e30f;
#pragma unroll
    for (int j = 0; j < 8; j++) {
        mx0 = fmaxf(mx0, fmaxf(s[j][0], s[j][1]));
        mx1 = fmaxf(mx1, fmaxf(s[j][2], s[j][3]));
    }
    mx0 = fmaxf(mx0, __shfl_xor_sync(0xffffffffu, mx0, 1));
    mx0 = fmaxf(mx0, __shfl_xor_sync(0xffffffffu, mx0, 2));
    mx1 = fmaxf(mx1, __shfl_xor_sync(0xffffffffu, mx1, 1));
    mx1 = fmaxf(mx1, __shfl_xor_sync(0xffffffffu, mx1, 2));

    float sm0 = 0.f, sm1 = 0.f;
#pragma unroll
    for (int j = 0; j < 8; j++) {
        s[j][0] = expf(s[j][0] - mx0); sm0 += s[j][0];
        s[j][1] = expf(s[j][1] - mx0); sm0 += s[j][1];
        s[j][2] = expf(s[j][2] - mx1); sm1 += s[j][2];
        s[j][3] = expf(s[j][3] - mx1); sm1 += s[j][3];
    }
    sm0 += __shfl_xor_sync(0xffffffffu, sm0, 1);
    sm0 += __shfl_xor_sync(0xffffffffu, sm0, 2);
    sm1 += __shfl_xor_sync(0xffffffffu, sm1, 1);
    sm1 += __shfl_xor_sync(0xffffffffu, sm1, 2);
    float inv0 = 1.f / sm0, inv1 = 1.f / sm1;

    float o[8][4];
#pragma unroll
    for (int j = 0; j < 8; j++)
#pragma unroll
        for (int e = 0; e < 4; e++) o[j][e] = 0.f;

#pragma unroll
    for (int kk = 0; kk < 4; kk++) {
        uint32_t a[4];
        a[0] = packh2(s[2 * kk][0] * inv0, s[2 * kk][1] * inv0);
        a[1] = packh2(s[2 * kk][2] * inv1, s[2 * kk][3] * inv1);
        a[2] = packh2(s[2 * kk + 1][0] * inv0, s[2 * kk + 1][1] * inv0);
        a[3] = packh2(s[2 * kk + 1][2] * inv1, s[2 * kk + 1][3] * inv1);
        int kb = kk * 32 + ((lane >> 4) & 1) * 16;
#pragma unroll
        for (int nf = 0; nf < 4; nf++) {
            uint32_t bh[4];
            ldsm4(bh, hb + 16384 + SWZ((uint32_t)((nf * 16 + (lane & 15)) * 128 + kb)));
            mma16816(o[nf * 2 + 0], a, bh[0], bh[2]);
            mma16816(o[nf * 2 + 1], a, bh[1], bh[3]);
        }
    }

    int r0 = base + wm + (lane >> 2);
    int r1 = r0 + 8;
#pragma unroll
    for (int j = 0; j < 8; j++) {
        int col = j * 8 + (lane & 3) * 2;
        if (r0 >= 0 && r0 < Tt)
            *(__half2*)(aout + ((size_t)(b * Tt + r0)) * Dm + h * HDm + col) =
                __halves2half2(__float2half_rn(o[j][0]), __float2half_rn(o[j][1]));
        if (r1 >= 0 && r1 < Tt)
            *(__half2*)(aout + ((size_t)(b * Tt + r1)) * Dm + h * HDm + col) =
                __halves2half2(__float2half_rn(o[j][2]), __float2half_rn(o[j][3]));
    }
}

// ============================================================
// Host driver
// ============================================================
extern "C" void kernel_launch(void* const* d_in, const int* in_sizes, int n_in,
                              void* d_out, int out_size) {
    const int*   inputs = (const int*)  d_in[0];
    const float* embed  = (const float*)d_in[1];
    const float* wq     = (const float*)d_in[2];
    const float* wk     = (const float*)d_in[3];
    const float* wv     = (const float*)d_in[4];
    const float* wo     = (const float*)d_in[5];
    const float* ln1_s  = (const float*)d_in[6];
    const float* ln1_b  = (const float*)d_in[7];
    const float* ln2_s  = (const float*)d_in[8];
    const float* ln2_b  = (const float*)d_in[9];
    const float* w1     = (const float*)d_in[10];
    const float* b1     = (const float*)d_in[11];
    const float* w2     = (const float*)d_in[12];
    const float* b2     = (const float*)d_in[13];
    const float* lnf_s  = (const float*)d_in[14];
    const float* lnf_b  = (const float*)d_in[15];

    float *x, *pe;
    __half *qkvh, *h, *a, *m, *wh;
    cudaGetSymbolAddress((void**)&x,    g_x);
    cudaGetSymbolAddress((void**)&pe,   g_pe);
    cudaGetSymbolAddress((void**)&qkvh, g_qkvh);
    cudaGetSymbolAddress((void**)&h,    g_h);
    cudaGetSymbolAddress((void**)&a,    g_a);
    cudaGetSymbolAddress((void**)&m,    g_m);
    cudaGetSymbolAddress((void**)&wh,   g_wh);

    // instantiations:      F16A ACC  RELU BIAS WF32 WHF
    auto kQKV  = hgemm<true, false,false,false,false,true >;
    auto kWO   = hgemm<true, true, false,false,true, false>;
    auto kMLP1 = hgemm<true, false,true, true, false,true >;
    auto kMLP2 = hgemm<false,true, false,true, true, false>;
    cudaFuncSetAttribute(kQKV,  cudaFuncAttributeMaxDynamicSharedMemorySize, SMEM_GEMM);
    cudaFuncSetAttribute(kWO,   cudaFuncAttributeMaxDynamicSharedMemorySize, SMEM_GEMM);
    cudaFuncSetAttribute(kMLP1, cudaFuncAttributeMaxDynamicSharedMemorySize, SMEM_GEMM);
    cudaFuncSetAttribute(kMLP2, cudaFuncAttributeMaxDynamicSharedMemorySize, SMEM_GEMM);
    cudaFuncSetAttribute(attn_mma, cudaFuncAttributeMaxDynamicSharedMemorySize, SMEM_ATTN);

    wprep_all<<<18432, dim3(32, 8)>>>(wq, wk, wv, wo, w1, w2, wh);
    pe_kernel<<<(Tt * 256) / 256, 256>>>(pe);
    embed_kernel<<<(TOK * Dm / 4) / 256, 256>>>(inputs, embed, pe, x);

    dim3 gQKV(1536 / 128, TOK / 128);
    dim3 gP(Dm / 128, TOK / 128);
    dim3 gM1(MLPD / 128, TOK / 128);
    int gLN = (TOK / 2 * 32) / 256;   // 2 tokens per warp

    for (int l = 0; l < Lnum; l++) {
        int lp = (l & 1) ? 32 : 0;
        int nb = (l & 1) ? (Tt + 64) / 64 : Tt / 64;

        ln_warp<true><<<gLN, 256>>>(x, ln1_s + l * Dm, ln1_b + l * Dm, h, nullptr);

        kQKV<<<gQKV, 256, SMEM_GEMM>>>(
            h, wh + OFF_QKV + (size_t)l * SZ_QKV,
            nullptr, nullptr, qkvh, 1536, Dm);

        attn_mma<<<dim3(nb, Hh / 2, Bb), 256, SMEM_ATTN>>>(qkvh, inputs, a, lp);

        kWO<<<gP, 256, SMEM_GEMM>>>(
            a, wh + OFF_WO + (size_t)l * WSZP,
            nullptr, x, nullptr, Dm, Dm);

        ln_warp<true><<<gLN, 256>>>(x, ln2_s + l * Dm, ln2_b + l * Dm, h, nullptr);

        kMLP1<<<gM1, 256, SMEM_GEMM>>>(
            h, wh + OFF_W1 + (size_t)l * WSZM,
            b1 + (size_t)l * MLPD, nullptr, m, MLPD, Dm);

        kMLP2<<<gP, 256, SMEM_GEMM>>>(
            m, wh + OFF_W2 + (size_t)l * WSZM,
            b2 + (size_t)l * Dm, x, nullptr, Dm, MLPD);
    }

    ln_warp<false><<<gLN, 256>>>(x, lnf_s, lnf_b, nullptr, (float*)d_out);
}

// round 16
// speedup vs baseline: 1.5114x; 1.0036x over previous
#include <cuda_runtime.h>
#include <cuda_fp16.h>
#include <math.h>
#include <stdint.h>

#define TOK   16384
#define Dm    512
#define Tt    4096
#define Bb    4
#define Hh    8
#define HDm   64
#define Lnum  6
#define MLPD  2048

#define WSZP  (Dm*Dm)
#define WSZM  (Dm*MLPD)
#define SZ_QKV (3*WSZP)
#define OFF_QKV 0
#define OFF_WO (6*SZ_QKV)
#define OFF_W1 (OFF_WO + 6*WSZP)
#define OFF_W2 (OFF_W1 + 6*WSZM)
#define WTOT   (OFF_W2 + 6*WSZM)

// ---------------- scratch (device globals) ----------------
__device__ __align__(128) float g_x[TOK * Dm];
__device__ __align__(128) float g_pe[Tt * Dm];
__device__ __align__(128) __half g_qkvh[TOK * 3 * Dm];
__device__ __align__(128) __half g_h[TOK * Dm];
__device__ __align__(128) __half g_a[TOK * Dm];
__device__ __align__(128) __half g_m[(size_t)TOK * MLPD];
__device__ __align__(128) __half g_wh[WTOT];

// ---------------- helpers ----------------
__device__ __forceinline__ uint32_t smem_u32(const void* p) {
    uint32_t a;
    asm("{ .reg .u64 t; cvta.to.shared.u64 t, %1; cvt.u32.u64 %0, t; }" : "=r"(a) : "l"(p));
    return a;
}
#define SWZ(o) ((o) ^ (((o) >> 3) & 0x70))

#define CP16(dst, src) \
    asm volatile("cp.async.cg.shared.global [%0], [%1], 16;" :: "r"(dst), "l"(src) : "memory")
#define CP_COMMIT() asm volatile("cp.async.commit_group;" ::: "memory")
#define CP_WAIT(n)  asm volatile("cp.async.wait_group %0;" :: "n"(n) : "memory")

__device__ __forceinline__ void ldsm4(uint32_t* r, uint32_t a) {
    asm volatile("ldmatrix.sync.aligned.m8n8.x4.shared.b16 {%0,%1,%2,%3}, [%4];"
                 : "=r"(r[0]), "=r"(r[1]), "=r"(r[2]), "=r"(r[3]) : "r"(a));
}
__device__ __forceinline__ void mma16816(float* c, const uint32_t* a,
                                         uint32_t b0, uint32_t b1) {
    asm volatile("mma.sync.aligned.m16n8k16.row.col.f32.f16.f16.f32 "
                 "{%0,%1,%2,%3},{%4,%5,%6,%7},{%8,%9},{%0,%1,%2,%3};"
                 : "+f"(c[0]), "+f"(c[1]), "+f"(c[2]), "+f"(c[3])
                 : "r"(a[0]), "r"(a[1]), "r"(a[2]), "r"(a[3]), "r"(b0), "r"(b1));
}
__device__ __forceinline__ void mma16816_h(uint32_t* c, const uint32_t* a,
                                           uint32_t b0, uint32_t b1) {
    asm volatile("mma.sync.aligned.m16n8k16.row.col.f16.f16.f16.f16 "
                 "{%0,%1},{%2,%3,%4,%5},{%6,%7},{%0,%1};"
                 : "+r"(c[0]), "+r"(c[1])
                 : "r"(a[0]), "r"(a[1]), "r"(a[2]), "r"(a[3]), "r"(b0), "r"(b1));
}
__device__ __forceinline__ uint32_t packh2(float a, float b) {
    __half2 h = __halves2half2(__float2half_rn(a), __float2half_rn(b));
    return *(uint32_t*)&h;
}

// ============================================================
// PE table
// ============================================================
__global__ void pe_kernel(float* __restrict__ pe) {
    int id = blockIdx.x * blockDim.x + threadIdx.x;
    int pos = id >> 8, i = id & 255;
    const float c = (float)(-9.210340371976184 / 512.0);
    float div = expf((float)(2 * i) * c);
    float ang = (float)pos * div;
    float s, co;
    sincosf(ang, &s, &co);
    pe[pos * Dm + i] = s;
    pe[pos * Dm + i + 256] = co;
}

// ============================================================
// Embedding + PE + fused LN1 (layer 0).
// Warp-per-token: x = embed[tok]+pe; stats in-warp; h = LN1_0(x).
// ============================================================
__global__ void embed_ln(const int* __restrict__ inputs,
                         const float* __restrict__ embed,
                         const float* __restrict__ pe,
                         const float* __restrict__ sc,
                         const float* __restrict__ bi,
                         float* __restrict__ x,
                         __half* __restrict__ oh) {
    int t = (blockIdx.x * blockDim.x + threadIdx.x) >> 5;
    int lane = threadIdx.x & 31;
    int pos = t & (Tt - 1);
    int tok = inputs[t];
    const float4* er = (const float4*)(embed + (size_t)tok * Dm);
    const float4* pr = (const float4*)(pe + (size_t)pos * Dm);

    float4 v[4];
    float s = 0.f, sq = 0.f;
#pragma unroll
    for (int i = 0; i < 4; i++) {
        int c4 = lane + 32 * i;
        float4 e = er[c4];
        float4 p = pr[c4];
        v[i] = make_float4(e.x + p.x, e.y + p.y, e.z + p.z, e.w + p.w);
        ((float4*)(x + (size_t)t * Dm))[c4] = v[i];
        s  += v[i].x + v[i].y + v[i].z + v[i].w;
        sq += v[i].x * v[i].x + v[i].y * v[i].y + v[i].z * v[i].z + v[i].w * v[i].w;
    }
#pragma unroll
    for (int o = 16; o; o >>= 1) {
        s  += __shfl_xor_sync(0xffffffffu, s, o);
        sq += __shfl_xor_sync(0xffffffffu, sq, o);
    }
    float mean = s * (1.f / 512.f);
    float rstd = rsqrtf(sq * (1.f / 512.f) - mean * mean + 1e-6f);

#pragma unroll
    for (int i = 0; i < 4; i++) {
        int c4 = lane + 32 * i;
        float4 s4 = ((const float4*)sc)[c4];
        float4 b4 = ((const float4*)bi)[c4];
        float y0 = (v[i].x - mean) * rstd * s4.x + b4.x;
        float y1 = (v[i].y - mean) * rstd * s4.y + b4.y;
        float y2 = (v[i].z - mean) * rstd * s4.z + b4.z;
        float y3 = (v[i].w - mean) * rstd * s4.w + b4.w;
        ((uint2*)(oh + (size_t)t * Dm))[c4] = make_uint2(packh2(y0, y1), packh2(y2, y3));
    }
}

// ============================================================
// Fused weight prep (one launch): fp32 [K][N] -> fp16 [N][K]
// ============================================================
__global__ void wprep_all(const float* __restrict__ wq, const float* __restrict__ wk,
                          const float* __restrict__ wv, const float* __restrict__ wo,
                          const float* __restrict__ w1, const float* __restrict__ w2,
                          __half* __restrict__ wh) {
    __shared__ float tt[32][33];
    int t = blockIdx.x;
    const float* src;
    __half* dh;
    int srcN, dstK, n0, k0, nd;

    if (t < 4608) {
        int g = t / 1536, r = t % 1536;
        int l = r >> 8, rr = r & 255;
        n0 = (rr & 15) << 5; k0 = (rr >> 4) << 5;
        const float* w = (g == 0) ? wq : (g == 1) ? wk : wv;
        src = w + (size_t)l * WSZP;
        dh = wh + OFF_QKV + (size_t)l * SZ_QKV;
        srcN = 512; dstK = 512; nd = g * 512 + n0;
    } else if (t < 6144) {
        int r = t - 4608;
        int l = r >> 8, rr = r & 255;
        n0 = (rr & 15) << 5; k0 = (rr >> 4) << 5;
        src = wo + (size_t)l * WSZP;
        dh = wh + OFF_WO + (size_t)l * WSZP;
        srcN = 512; dstK = 512; nd = n0;
    } else if (t < 12288) {
        int r = t - 6144;
        int l = r >> 10, rr = r & 1023;
        n0 = (rr & 63) << 5; k0 = (rr >> 6) << 5;
        src = w1 + (size_t)l * WSZM;
        dh = wh + OFF_W1 + (size_t)l * WSZM;
        srcN = 2048; dstK = 512; nd = n0;
    } else {
        int r = t - 12288;
        int l = r >> 10, rr = r & 1023;
        n0 = (rr & 15) << 5; k0 = (rr >> 4) << 5;
        src = w2 + (size_t)l * WSZM;
        dh = wh + OFF_W2 + (size_t)l * WSZM;
        srcN = 512; dstK = 2048; nd = n0;
    }

    int tx = threadIdx.x, ty = threadIdx.y;
#pragma unroll
    for (int i = 0; i < 4; i++)
        tt[ty + i * 8][tx] = src[(size_t)(k0 + ty + i * 8) * srcN + n0 + tx];
    __syncthreads();
#pragma unroll
    for (int i = 0; i < 4; i++) {
        float v = tt[tx][ty + i * 8];
        dh[(size_t)(nd + ty + i * 8) * dstK + k0 + tx] = __float2half_rn(v);
    }
}

// ============================================================
// Warp-per-2-tokens single-pass LayerNorm (R15-proven).
// ============================================================
template <bool WHF>
__global__ void ln_warp(const float* __restrict__ x,
                        const float* __restrict__ sc,
                        const float* __restrict__ bi,
                        __half* __restrict__ oh,
                        float* __restrict__ outf) {
    int w = (blockIdx.x * blockDim.x + threadIdx.x) >> 5;
    int lane = threadIdx.x & 31;
    int t0 = w * 2;
    const float4* xr0 = (const float4*)(x + (size_t)t0 * Dm);
    const float4* xr1 = (const float4*)(x + (size_t)(t0 + 1) * Dm);

    float4 v0[4], v1[4];
    float s0 = 0.f, q0 = 0.f, s1 = 0.f, q1 = 0.f;
#pragma unroll
    for (int i = 0; i < 4; i++) {
        v0[i] = xr0[lane + 32 * i];
        v1[i] = xr1[lane + 32 * i];
        s0 += v0[i].x + v0[i].y + v0[i].z + v0[i].w;
        q0 += v0[i].x * v0[i].x + v0[i].y * v0[i].y + v0[i].z * v0[i].z + v0[i].w * v0[i].w;
        s1 += v1[i].x + v1[i].y + v1[i].z + v1[i].w;
        q1 += v1[i].x * v1[i].x + v1[i].y * v1[i].y + v1[i].z * v1[i].z + v1[i].w * v1[i].w;
    }
#pragma unroll
    for (int o = 16; o; o >>= 1) {
        s0 += __shfl_xor_sync(0xffffffffu, s0, o);
        q0 += __shfl_xor_sync(0xffffffffu, q0, o);
        s1 += __shfl_xor_sync(0xffffffffu, s1, o);
        q1 += __shfl_xor_sync(0xffffffffu, q1, o);
    }
    float mean0 = s0 * (1.f / 512.f);
    float rstd0 = rsqrtf(q0 * (1.f / 512.f) - mean0 * mean0 + 1e-6f);
    float mean1 = s1 * (1.f / 512.f);
    float rstd1 = rsqrtf(q1 * (1.f / 512.f) - mean1 * mean1 + 1e-6f);

#pragma unroll
    for (int i = 0; i < 4; i++) {
        int c4 = lane + 32 * i;
        float4 s4 = ((const float4*)sc)[c4];
        float4 b4 = ((const float4*)bi)[c4];
        float a0 = (v0[i].x - mean0) * rstd0 * s4.x + b4.x;
        float a1 = (v0[i].y - mean0) * rstd0 * s4.y + b4.y;
        float a2 = (v0[i].z - mean0) * rstd0 * s4.z + b4.z;
        float a3 = (v0[i].w - mean0) * rstd0 * s4.w + b4.w;
        float c0 = (v1[i].x - mean1) * rstd1 * s4.x + b4.x;
        float c1 = (v1[i].y - mean1) * rstd1 * s4.y + b4.y;
        float c2 = (v1[i].z - mean1) * rstd1 * s4.z + b4.z;
        float c3 = (v1[i].w - mean1) * rstd1 * s4.w + b4.w;
        if (WHF) {
            ((uint2*)(oh + (size_t)t0 * Dm))[c4] = make_uint2(packh2(a0, a1), packh2(a2, a3));
            ((uint2*)(oh + (size_t)(t0 + 1) * Dm))[c4] = make_uint2(packh2(c0, c1), packh2(c2, c3));
        } else {
            ((float4*)(outf + (size_t)t0 * Dm))[c4] = make_float4(a0, a1, a2, a3);
            ((float4*)(outf + (size_t)(t0 + 1) * Dm))[c4] = make_float4(c0, c1, c2, c3);
        }
    }
}

// ============================================================
// HMMA fp16 GEMM (R11-proven): C[M,N] (+)= A @ B^T
// ============================================================
#define ST_B    16384
#define STAGE   32768
#define SMEM_GEMM (3 * STAGE)

template <bool F16A, bool ACCUM, bool RELU, bool BIAS, bool WF32, bool WHF>
__global__ void __launch_bounds__(256, 2)
hgemm(const __half* __restrict__ A, const __half* __restrict__ B,
      const float* __restrict__ bias, float* __restrict__ C,
      __half* __restrict__ O,
      int N, int K) {
    extern __shared__ char smem[];
    uint32_t sb = smem_u32(smem);
    int tid = threadIdx.x, wid = tid >> 5, lane = tid & 31;
    int m0 = blockIdx.y * 128, n0 = blockIdx.x * 128;
    int wm = (wid >> 1) * 32, wn = (wid & 1) * 64;

    float accf[2][8][4];
    uint32_t acch[2][8][2];
    if (F16A) {
#pragma unroll
        for (int i = 0; i < 2; i++)
#pragma unroll
            for (int j = 0; j < 8; j++) { acch[i][j][0] = 0u; acch[i][j][1] = 0u; }
    } else {
#pragma unroll
        for (int i = 0; i < 2; i++)
#pragma unroll
            for (int j = 0; j < 8; j++)
#pragma unroll
                for (int e = 0; e < 4; e++) accf[i][j][e] = 0.f;
    }

    const int NC = K >> 6;

#define LOAD_CHUNK(c, s) do {                                                   \
    int kt = (c) << 6;                                                          \
    uint32_t st_ = sb + (s) * STAGE;                                            \
    _Pragma("unroll")                                                           \
    for (int i = 0; i < 4; i++) {                                               \
        int u = tid + i * 256;                                                  \
        int row = u >> 3, kc = u & 7;                                           \
        uint32_t so = SWZ((uint32_t)(row * 128 + kc * 16));                     \
        size_t ga = (size_t)(m0 + row) * K + kt + kc * 8;                       \
        size_t gb = (size_t)(n0 + row) * K + kt + kc * 8;                       \
        CP16(st_ + so,        A + ga);                                          \
        CP16(st_ + ST_B + so, B + gb);                                          \
    } } while (0)

    LOAD_CHUNK(0, 0);
    CP_COMMIT();
    LOAD_CHUNK(1, 1);
    CP_COMMIT();

    for (int c = 0; c < NC; c++) {
        if (c + 1 < NC) { CP_WAIT(1); } else { CP_WAIT(0); }
        __syncthreads();
        if (c + 2 < NC) {
            LOAD_CHUNK(c + 2, (c + 2) % 3);
            CP_COMMIT();
        }
        uint32_t st = sb + (c % 3) * STAGE;

#pragma unroll
        for (int ks = 0; ks < 4; ks++) {
            int kb = ks * 32 + ((lane >> 4) & 1) * 16;
            uint32_t ah[2][4];
#pragma unroll
            for (int mf = 0; mf < 2; mf++) {
                uint32_t ro = (uint32_t)((wm + mf * 16 + (lane & 15)) * 128 + kb);
                ldsm4(ah[mf], st + SWZ(ro));
            }
#pragma unroll
            for (int nf = 0; nf < 4; nf++) {
                uint32_t bh[4];
                uint32_t ro = (uint32_t)((wn + nf * 16 + (lane & 15)) * 128 + kb);
                ldsm4(bh, st + ST_B + SWZ(ro));
#pragma unroll
                for (int mf = 0; mf < 2; mf++)
#pragma unroll
                    for (int sl = 0; sl < 2; sl++) {
                        if (F16A)
                            mma16816_h(acch[mf][nf * 2 + sl], ah[mf], bh[sl], bh[sl + 2]);
                        else
                            mma16816(accf[mf][nf * 2 + sl], ah[mf], bh[sl], bh[sl + 2]);
                    }
            }
        }
    }

    // epilogue
    int r0 = m0 + wm + (lane >> 2);
    int cb = n0 + wn + (lane & 3) * 2;
#pragma unroll
    for (int mf = 0; mf < 2; mf++)
#pragma unroll
        for (int hf = 0; hf < 2; hf++) {
            int rr = r0 + mf * 16 + hf * 8;
#pragma unroll
            for (int nb = 0; nb < 8; nb++) {
                int cc = cb + nb * 8;
                if (F16A && WHF && !BIAS && !RELU && !ACCUM) {
                    *(uint32_t*)(O + (size_t)rr * N + cc) = acch[mf][nb][hf];
                    continue;
                }
                float v0, v1;
                if (F16A) {
                    __half2 hv = *(__half2*)&acch[mf][nb][hf];
                    v0 = __low2float(hv);
                    v1 = __high2float(hv);
                } else {
                    v0 = accf[mf][nb][hf * 2 + 0];
                    v1 = accf[mf][nb][hf * 2 + 1];
                }
                if (BIAS) {
                    float2 bv = *(const float2*)(bias + cc);
                    v0 += bv.x; v1 += bv.y;
                }
                if (RELU) { v0 = fmaxf(v0, 0.f); v1 = fmaxf(v1, 0.f); }
                if (ACCUM) {
                    atomicAdd(C + (size_t)rr * N + cc, v0);
                    atomicAdd(C + (size_t)rr * N + cc + 1, v1);
                } else if (WF32) {
                    *(float2*)(C + (size_t)rr * N + cc) = make_float2(v0, v1);
                }
                if (WHF)
                    *(__half2*)(O + (size_t)rr * N + cc) =
                        __halves2half2(__float2half_rn(v0), __float2half_rn(v1));
            }
        }
#undef LOAD_CHUNK
}

// ============================================================
// Tensor-core local block attention — 2 heads per CTA (R15-proven).
// ============================================================
#define AT_HEAD 24576
#define AT_MK   49152
#define SMEM_ATTN (49152 + 256)

__global__ void __launch_bounds__(256)
attn_mma(const __half* __restrict__ qkvh,
         const int* __restrict__ inputs,
         __half* __restrict__ aout,
         int lp) {
    extern __shared__ __align__(16) char smem[];
    uint32_t sb = smem_u32(smem);
    float* maskS = (float*)(smem + AT_MK);

    int n = blockIdx.x, h0 = blockIdx.y * 2, b = blockIdx.z;
    int tid = threadIdx.x, wid = tid >> 5, lane = tid & 31;
    int base = n * 64 - lp;

#pragma unroll
    for (int hh = 0; hh < 2; hh++) {
        char* hs = smem + hh * AT_HEAD;
#pragma unroll
        for (int i = 0; i < 2; i++) {
            int u = tid + i * 256;
            int row = u >> 3, c = u & 7;
            int gt = base + row;
            uint4 qv = make_uint4(0, 0, 0, 0), kv = qv, vv = qv;
            if (gt >= 0 && gt < Tt) {
                const __half* p = qkvh + ((size_t)(b * Tt + gt)) * 1536 + (h0 + hh) * HDm;
                qv = *(const uint4*)(p + c * 8);
                kv = *(const uint4*)(p + 512 + c * 8);
                vv = *(const uint4*)(p + 1024 + c * 8);
            }
            uint32_t so = SWZ((uint32_t)(row * 128 + c * 16));
            *(uint4*)(hs + so) = qv;
            *(uint4*)(hs + 8192 + so) = kv;
            __half vh[8];
            *(uint4*)vh = vv;
#pragma unroll
            for (int j = 0; j < 8; j++) {
                uint32_t off = (uint32_t)((c * 8 + j) * 128 + row * 2);
                *(__half*)(hs + 16384 + SWZ(off)) = vh[j];
            }
        }
    }
    if (tid < 64) {
        int gt = base + tid;
        maskS[tid] = (gt >= 0 && gt < Tt && inputs[b * Tt + gt] > 0) ? 1.f : 0.f;
    }
    __syncthreads();

    int hh = wid >> 2;
    int wm = (wid & 3) * 16;
    uint32_t hb = sb + hh * AT_HEAD;
    int h = h0 + hh;

    float s[8][4];
#pragma unroll
    for (int j = 0; j < 8; j++)
#pragma unroll
        for (int e = 0; e < 4; e++) s[j][e] = 0.f;

#pragma unroll
    for (int ks = 0; ks < 4; ks++) {
        int kb = ks * 32 + ((lane >> 4) & 1) * 16;
        uint32_t a[4];
        ldsm4(a, hb + SWZ((uint32_t)((wm + (lane & 15)) * 128 + kb)));
#pragma unroll
        for (int nf = 0; nf < 4; nf++) {
            uint32_t bh[4];
            ldsm4(bh, hb + 8192 + SWZ((uint32_t)((nf * 16 + (lane & 15)) * 128 + kb)));
            mma16816(s[nf * 2 + 0], a, bh[0], bh[2]);
            mma16816(s[nf * 2 + 1], a, bh[1], bh[3]);
        }
    }

#pragma unroll
    for (int j = 0; j < 8; j++) {
        int col = j * 8 + (lane & 3) * 2;
        float m0 = maskS[col], m1 = maskS[col + 1];
        s[j][0] = (m0 > 0.f) ? s[j][0] * 0.125f : -1e9f;
        s[j][2] = (m0 > 0.f) ? s[j][2] * 0.125f : -1e9f;
        s[j][1] = (m1 > 0.f) ? s[j][1] * 0.125f : -1e9f;
        s[j][3] = (m1 > 0.f) ? s[j][3] * 0.125f : -1e9f;
    }

    float mx0 = -1e30f, mx1 = -1e30f;
#pragma unroll
    for (int j = 0; j < 8; j++) {
        mx0 = fmaxf(mx0, fmaxf(s[j][0], s[j][1]));
        mx1 = fmaxf(mx1, fmaxf(s[j][2], s[j][3]));
    }
    mx0 = fmaxf(mx0, __shfl_xor_sync(0xffffffffu, mx0, 1));
    mx0 = fmaxf(mx0, __shfl_xor_sync(0xffffffffu, mx0, 2));
    mx1 = fmaxf(mx1, __shfl_xor_sync(0xffffffffu, mx1, 1));
    mx1 = fmaxf(mx1, __shfl_xor_sync(0xffffffffu, mx1, 2));

    float sm0 = 0.f, sm1 = 0.f;
#pragma unroll
    for (int j = 0; j < 8; j++) {
        s[j][0] = expf(s[j][0] - mx0); sm0 += s[j][0];
        s[j][1] = expf(s[j][1] - mx0); sm0 += s[j][1];
        s[j][2] = expf(s[j][2] - mx1); sm1 += s[j][2];
        s[j][3] = expf(s[j][3] - mx1); sm1 += s[j][3];
    }
    sm0 += __shfl_xor_sync(0xffffffffu, sm0, 1);
    sm0 += __shfl_xor_sync(0xffffffffu, sm0, 2);
    sm1 += __shfl_xor_sync(0xffffffffu, sm1, 1);
    sm1 += __shfl_xor_sync(0xffffffffu, sm1, 2);
    float inv0 = 1.f / sm0, inv1 = 1.f / sm1;

    float o[8][4];
#pragma unroll
    for (int j = 0; j < 8; j++)
#pragma unroll
        for (int e = 0; e < 4; e++) o[j][e] = 0.f;

#pragma unroll
    for (int kk = 0; kk < 4; kk++) {
        uint32_t a[4];
        a[0] = packh2(s[2 * kk][0] * inv0, s[2 * kk][1] * inv0);
        a[1] = packh2(s[2 * kk][2] * inv1, s[2 * kk][3] * inv1);
        a[2] = packh2(s[2 * kk + 1][0] * inv0, s[2 * kk + 1][1] * inv0);
        a[3] = packh2(s[2 * kk + 1][2] * inv1, s[2 * kk + 1][3] * inv1);
        int kb = kk * 32 + ((lane >> 4) & 1) * 16;
#pragma unroll
        for (int nf = 0; nf < 4; nf++) {
            uint32_t bh[4];
            ldsm4(bh, hb + 16384 + SWZ((uint32_t)((nf * 16 + (lane & 15)) * 128 + kb)));
            mma16816(o[nf * 2 + 0], a, bh[0], bh[2]);
            mma16816(o[nf * 2 + 1], a, bh[1], bh[3]);
        }
    }

    int r0 = base + wm + (lane >> 2);
    int r1 = r0 + 8;
#pragma unroll
    for (int j = 0; j < 8; j++) {
        int col = j * 8 + (lane & 3) * 2;
        if (r0 >= 0 && r0 < Tt)
            *(__half2*)(aout + ((size_t)(b * Tt + r0)) * Dm + h * HDm + col) =
                __halves2half2(__float2half_rn(o[j][0]), __float2half_rn(o[j][1]));
        if (r1 >= 0 && r1 < Tt)
            *(__half2*)(aout + ((size_t)(b * Tt + r1)) * Dm + h * HDm + col) =
                __halves2half2(__float2half_rn(o[j][2]), __float2half_rn(o[j][3]));
    }
}

// ============================================================
// Host driver
// ============================================================
extern "C" void kernel_launch(void* const* d_in, const int* in_sizes, int n_in,
                              void* d_out, int out_size) {
    const int*   inputs = (const int*)  d_in[0];
    const float* embed  = (const float*)d_in[1];
    const float* wq     = (const float*)d_in[2];
    const float* wk     = (const float*)d_in[3];
    const float* wv     = (const float*)d_in[4];
    const float* wo     = (const float*)d_in[5];
    const float* ln1_s  = (const float*)d_in[6];
    const float* ln1_b  = (const float*)d_in[7];
    const float* ln2_s  = (const float*)d_in[8];
    const float* ln2_b  = (const float*)d_in[9];
    const float* w1     = (const float*)d_in[10];
    const float* b1     = (const float*)d_in[11];
    const float* w2     = (const float*)d_in[12];
    const float* b2     = (const float*)d_in[13];
    const float* lnf_s  = (const float*)d_in[14];
    const float* lnf_b  = (const float*)d_in[15];

    float *x, *pe;
    __half *qkvh, *h, *a, *m, *wh;
    cudaGetSymbolAddress((void**)&x,    g_x);
    cudaGetSymbolAddress((void**)&pe,   g_pe);
    cudaGetSymbolAddress((void**)&qkvh, g_qkvh);
    cudaGetSymbolAddress((void**)&h,    g_h);
    cudaGetSymbolAddress((void**)&a,    g_a);
    cudaGetSymbolAddress((void**)&m,    g_m);
    cudaGetSymbolAddress((void**)&wh,   g_wh);

    // instantiations:      F16A ACC  RELU BIAS WF32 WHF
    auto kQKV  = hgemm<true, false,false,false,false,true >;
    auto kWO   = hgemm<true, true, false,false,true, false>;
    auto kMLP1 = hgemm<true, false,true, true, false,true >;
    auto kMLP2 = hgemm<false,true, false,true, true, false>;
    cudaFuncSetAttribute(kQKV,  cudaFuncAttributeMaxDynamicSharedMemorySize, SMEM_GEMM);
    cudaFuncSetAttribute(kWO,   cudaFuncAttributeMaxDynamicSharedMemorySize, SMEM_GEMM);
    cudaFuncSetAttribute(kMLP1, cudaFuncAttributeMaxDynamicSharedMemorySize, SMEM_GEMM);
    cudaFuncSetAttribute(kMLP2, cudaFuncAttributeMaxDynamicSharedMemorySize, SMEM_GEMM);
    cudaFuncSetAttribute(attn_mma, cudaFuncAttributeMaxDynamicSharedMemorySize, SMEM_ATTN);

    wprep_all<<<18432, dim3(32, 8)>>>(wq, wk, wv, wo, w1, w2, wh);
    pe_kernel<<<(Tt * 256) / 256, 256>>>(pe);
    // embed + PE + LN1(layer 0) fused: writes x AND h
    embed_ln<<<(TOK * 32) / 256, 256>>>(inputs, embed, pe, ln1_s, ln1_b, x, h);

    dim3 gQKV(1536 / 128, TOK / 128);
    dim3 gP(Dm / 128, TOK / 128);
    dim3 gM1(MLPD / 128, TOK / 128);
    int gLN = (TOK / 2 * 32) / 256;   // 2 tokens per warp

    for (int l = 0; l < Lnum; l++) {
        int lp = (l & 1) ? 32 : 0;
        int nb = (l & 1) ? (Tt + 64) / 64 : Tt / 64;

        // h = LN1(x) — fused into embed for layer 0
        if (l > 0)
            ln_warp<true><<<gLN, 256>>>(x, ln1_s + l * Dm, ln1_b + l * Dm, h, nullptr);

        kQKV<<<gQKV, 256, SMEM_GEMM>>>(
            h, wh + OFF_QKV + (size_t)l * SZ_QKV,
            nullptr, nullptr, qkvh, 1536, Dm);

        attn_mma<<<dim3(nb, Hh / 2, Bb), 256, SMEM_ATTN>>>(qkvh, inputs, a, lp);

        kWO<<<gP, 256, SMEM_GEMM>>>(
            a, wh + OFF_WO + (size_t)l * WSZP,
            nullptr, x, nullptr, Dm, Dm);

        ln_warp<true><<<gLN, 256>>>(x, ln2_s + l * Dm, ln2_b + l * Dm, h, nullptr);

        kMLP1<<<gM1, 256, SMEM_GEMM>>>(
            h, wh + OFF_W1 + (size_t)l * WSZM,
            b1 + (size_t)l * MLPD, nullptr, m, MLPD, Dm);

        kMLP2<<<gP, 256, SMEM_GEMM>>>(
            m, wh + OFF_W2 + (size_t)l * WSZM,
            b2 + (size_t)l * Dm, x, nullptr, Dm, MLPD);
    }

    ln_warp<false><<<gLN, 256>>>(x, lnf_s, lnf_b, nullptr, (float*)d_out);
}